// round 4
// baseline (speedup 1.0000x reference)
#include <cuda_runtime.h>
#include <cuda_bf16.h>
#include <math.h>
#include <stdint.h>

#define D     128
#define KP    20
#define OUTD  128
#define VMAX  100000
#define EMAX  400000
#define EPS   1e-5f
#define NBMAX 1563   // (VMAX+63)/64

// ---------------- scratch (device globals; no allocations) ----------------
__device__ float g_npj  [VMAX * KP];
__device__ float g_logit[EMAX];
__device__ float g_aexp [EMAX];
__device__ float g_lmax [VMAX];
__device__ float g_asum [VMAX];
__device__ float g_hv   [VMAX * D];
__device__ float g_ctx  [VMAX * D];
__device__ float g_kf   [VMAX * OUTD];
__device__ float g_gi   [VMAX * 3 * D];
__device__ float g_gh   [VMAX * 3 * D];
__device__ float g_gru  [VMAX * D];
__device__ float g_kout [(size_t)EMAX * OUTD];   // per-edge kron rows (sorted order)

// CSR sort scratch
__device__ int g_cnt [VMAX];
__device__ int g_cnt2[VMAX];
__device__ int g_row [VMAX + 1];
__device__ int g_perm[EMAX];

// fragment-ordered bf16 hi/lo weight streams
__device__ uint32_t g_WpnS[1 * 4 * 4096];
__device__ uint32_t g_WihS[3 * 4 * 4096];
__device__ uint32_t g_WhhS[3 * 4 * 4096];
__device__ uint32_t g_WcS [1 * 8 * 4096];
__device__ uint32_t g_Wk2S[5 * 10240];

// fragment-ordered bf16 hi/lo activation streams
__device__ uint32_t g_Anode[(size_t)NBMAX * 4 * 4096];
__device__ uint32_t g_Actx [(size_t)NBMAX * 4 * 4096];
__device__ uint32_t g_Acat [(size_t)NBMAX * 8 * 4096];

// ---------------- fast bf16 hi/lo split (truncation) ----------------
__device__ __forceinline__ void split_pair(float a0, float a1,
                                           uint32_t& hi, uint32_t& lo) {
    uint32_t b0 = __float_as_uint(a0), b1 = __float_as_uint(a1);
    uint32_t hp;
    asm("prmt.b32 %0, %1, %2, 0x7632;" : "=r"(hp) : "r"(b0), "r"(b1));
    float l0 = a0 - __uint_as_float(b0 & 0xffff0000u);
    float l1 = a1 - __uint_as_float(b1 & 0xffff0000u);
    __nv_bfloat162 lp = __floats2bfloat162_rn(l0, l1);
    hi = hp;
    lo = *(uint32_t*)&lp;
}

#define MMA_BF16(c, A, B) asm volatile( \
    "mma.sync.aligned.m16n8k16.row.col.f32.bf16.bf16.f32 " \
    "{%0,%1,%2,%3}, {%4,%5,%6,%7}, {%8,%9}, {%0,%1,%2,%3};\n" \
    : "+f"(c[0]), "+f"(c[1]), "+f"(c[2]), "+f"(c[3]) \
    : "r"(A.x), "r"(A.y), "r"(A.z), "r"(A.w), "r"(B.x), "r"(B.y))

// ---------------- utility kernels ----------------
__global__ void zero_kernel(float4* p, int n4) {
    int i = blockIdx.x * blockDim.x + threadIdx.x;
    if (i < n4) p[i] = make_float4(0.f, 0.f, 0.f, 0.f);
}
__global__ void zeroi_kernel(int* p, int n) {
    int i = blockIdx.x * blockDim.x + threadIdx.x;
    if (i < n) p[i] = 0;
}

// ---------------- CSR build: hist -> scan -> scatter ----------------
__global__ void hist_kernel(const int* __restrict__ dst, int E) {
    int e = blockIdx.x * blockDim.x + threadIdx.x;
    if (e < E) atomicAdd(&g_cnt[dst[e]], 1);
}
__global__ void scan_kernel(int V, int E) {
    __shared__ int sums[1024];
    int t = threadIdx.x;
    int chunk = (V + 1023) >> 10;
    int lo = t * chunk, hi = lo + chunk; if (hi > V) hi = V; if (lo > V) lo = V;
    int s = 0;
    for (int i = lo; i < hi; i++) s += g_cnt[i];
    sums[t] = s;
    __syncthreads();
    for (int off = 1; off < 1024; off <<= 1) {
        int v = (t >= off) ? sums[t - off] : 0;
        __syncthreads();
        sums[t] += v;
        __syncthreads();
    }
    int base = (t == 0) ? 0 : sums[t - 1];
    for (int i = lo; i < hi; i++) { int c = g_cnt[i]; g_row[i] = base; base += c; }
    if (t == 0) g_row[V] = E;
}
__global__ void scatter_kernel(const int* __restrict__ dst, int E) {
    int e = blockIdx.x * blockDim.x + threadIdx.x;
    if (e >= E) return;
    int d = dst[e];
    int pos = g_row[d] + atomicAdd(&g_cnt2[d], 1);
    g_perm[pos] = e;
}

// pack weights into fragment stream
__global__ void pack_w_frag(const float* __restrict__ W, int K, int Ntot,
                            int transp, uint32_t* __restrict__ out) {
    int idx = blockIdx.x * blockDim.x + threadIdx.x;
    int total = (K / 2) * Ntot;
    if (idx >= total) return;
    int kp = idx / Ntot, n = idx - kp * Ntot;
    int k0 = 2 * kp;
    float w0, w1;
    if (transp) { w0 = W[n * K + k0]; w1 = W[n * K + k0 + 1]; }
    else        { w0 = W[k0 * Ntot + n]; w1 = W[(k0 + 1) * Ntot + n]; }
    int c = kp >> 4, kpl = kp & 15;
    int ny = n >> 7, nl = n & 127;
    int bi = ((((nl >> 3) * 2 + (kpl >> 3)) * 32 + ((nl & 7) << 2) + (kpl & 3)) << 1)
             + ((kpl >> 2) & 1);
    size_t base = ((size_t)(ny * (K >> 5) + c)) << 12;
    uint32_t hi, lo;
    split_pair(w0, w1, hi, lo);
    out[base + bi] = hi;
    out[base + 2048 + bi] = lo;
}

// Wk2 [400][128] -> kron stream
__global__ void pack_wk2(const float* __restrict__ W, uint32_t* __restrict__ out) {
    int idx = blockIdx.x * blockDim.x + threadIdx.x;
    if (idx >= 200 * 128) return;
    int kp = idx >> 7, n = idx & 127;
    float w0 = W[(2 * kp) * 128 + n];
    float w1 = W[(2 * kp + 1) * 128 + n];
    int c = kp / 40, kpl = kp - c * 40;
    int bi = ((((n >> 3) * 5 + (kpl >> 3)) * 32 + ((n & 7) << 2) + (kpl & 3)) << 1)
             + ((kpl >> 2) & 1);
    uint32_t hi, lo;
    split_pair(w0, w1, hi, lo);
    out[c * 10240 + bi] = hi;
    out[c * 10240 + 5120 + bi] = lo;
}

// pack fp32 activation into fragment stream
__global__ void pack_act(const float* __restrict__ X0, int K0,
                         const float* __restrict__ X1, int K1, int relu,
                         uint32_t* __restrict__ out, int V) {
    int t = threadIdx.x;
    int mb = blockIdx.x;
    int K = K0 + K1;
    int Kch = K >> 5;
    size_t obase = ((size_t)mb * Kch) << 12;
    for (int it = 0; it < Kch * 8; it++) {
        int c = it >> 3;
        int idx = ((it & 7) << 8) + t;
        int ri = idx & 3;
        int lane = (idx >> 2) & 31;
        int kstep = (idx >> 7) & 1;
        int mt = idx >> 8;
        int row = mb * 64 + mt * 16 + (ri & 1) * 8 + (lane >> 2);
        if (row >= V) row = V - 1;
        int kp = kstep * 8 + ((ri >> 1) << 2) + (lane & 3);
        int k = c * 32 + kp * 2;
        float2 a;
        if (k < K0) a = *(const float2*)&X0[(size_t)row * K0 + k];
        else        a = *(const float2*)&X1[(size_t)row * K1 + (k - K0)];
        if (relu) { a.x = fmaxf(a.x, 0.f); a.y = fmaxf(a.y, 0.f); }
        uint32_t hi, lo;
        split_pair(a.x, a.y, hi, lo);
        size_t base = obase + ((size_t)c << 12);
        out[base + idx] = hi;
        out[base + 2048 + idx] = lo;
    }
}

// ---------------- npj ----------------
__global__ void npj_kernel(const float* __restrict__ x,
                           const float* __restrict__ Wk1,
                           const float* __restrict__ bk1,
                           const float* __restrict__ g,
                           const float* __restrict__ b, int V) {
    __shared__ float xs[4][D];
    int warp = threadIdx.x >> 5, lane = threadIdx.x & 31;
    int v  = blockIdx.x * 4 + warp;
    int vc = v < V ? v : V - 1;
    *(float4*)&xs[warp][lane << 2] = *(const float4*)&x[vc * D + (lane << 2)];
    __syncwarp();
    float y = 0.f;
    if (lane < KP) {
        #pragma unroll 8
        for (int k = 0; k < D; k++) y = fmaf(xs[warp][k], Wk1[k * KP + lane], y);
        y += bk1[lane];
    }
    float s = (lane < KP) ? y : 0.f;
    #pragma unroll
    for (int m = 16; m; m >>= 1) s += __shfl_xor_sync(0xffffffffu, s, m);
    float mu = s * (1.f / KP);
    float dv = (lane < KP) ? (y - mu) * (y - mu) : 0.f;
    #pragma unroll
    for (int m = 16; m; m >>= 1) dv += __shfl_xor_sync(0xffffffffu, dv, m);
    float rstd = rsqrtf(dv * (1.f / KP) + EPS);
    if (v < V && lane < KP) {
        float val = (y - mu) * rstd * g[lane] + b[lane];
        g_npj[v * KP + lane] = fmaxf(val, 0.f);
    }
}

// ---------------- edge logits + segment max ----------------
__global__ void logits_kernel(const float* __restrict__ x,
                              const int* __restrict__ src,
                              const int* __restrict__ dst,
                              const float* __restrict__ We,
                              const float* __restrict__ be, int E) {
    int e = blockIdx.x * 4 + (threadIdx.x >> 5);
    if (e >= E) return;
    int lane = threadIdx.x & 31;
    int sn = src[e], dn = dst[e];
    float4 xd = *(const float4*)&x[dn * D + (lane << 2)];
    float4 w1 = *(const float4*)&We[lane << 2];
    float4 xv = *(const float4*)&x[sn * D + (lane << 2)];
    float4 w2 = *(const float4*)&We[D + (lane << 2)];
    float p = xd.x * w1.x + xd.y * w1.y + xd.z * w1.z + xd.w * w1.w
            + xv.x * w2.x + xv.y * w2.y + xv.z * w2.z + xv.w * w2.w;
    #pragma unroll
    for (int m = 16; m; m >>= 1) p += __shfl_xor_sync(0xffffffffu, p, m);
    if (lane == 0) {
        float lg = fmaxf(p + be[0], 0.f);
        g_logit[e] = lg;
        atomicMax((int*)&g_lmax[dn], __float_as_int(lg));  // valid: lg >= 0
    }
}

__global__ void expsum_kernel(const int* __restrict__ dst, int E) {
    int e = blockIdx.x * blockDim.x + threadIdx.x;
    if (e >= E) return;
    int dn = dst[e];
    float a = expf(g_logit[e] - g_lmax[dn]);
    g_aexp[e] = a;
    atomicAdd(&g_asum[dn], a);
}

// ---------------- context via CSR: ctx[v] = relu(sum hv[src[e]]*a/asum) ----
__global__ void ctx_csr(const int* __restrict__ src, int V) {
    int v = blockIdx.x * 8 + (threadIdx.x >> 5);
    if (v >= V) return;
    int lane = threadIdx.x & 31;
    int b = g_row[v], e2 = g_row[v + 1];
    float rinv = (e2 > b) ? (1.f / g_asum[v]) : 0.f;
    float4 acc = make_float4(0.f, 0.f, 0.f, 0.f);
    for (int p = b; p < e2; p++) {
        int pe = g_perm[p];
        float coef = g_aexp[pe] * rinv;
        float4 h = *(const float4*)&g_hv[(size_t)src[pe] * D + (lane << 2)];
        acc.x = fmaf(h.x, coef, acc.x);
        acc.y = fmaf(h.y, coef, acc.y);
        acc.z = fmaf(h.z, coef, acc.z);
        acc.w = fmaf(h.w, coef, acc.w);
    }
    acc.x = fmaxf(acc.x, 0.f); acc.y = fmaxf(acc.y, 0.f);
    acc.z = fmaxf(acc.z, 0.f); acc.w = fmaxf(acc.w, 0.f);
    *(float4*)&g_ctx[(size_t)v * D + (lane << 2)] = acc;
}

// ---------------- kf via CSR: kf[v] = sum of sorted kout rows ----------------
__global__ void kf_csr(int V) {
    int v = blockIdx.x * 8 + (threadIdx.x >> 5);
    if (v >= V) return;
    int lane = threadIdx.x & 31;
    int b = g_row[v], e2 = g_row[v + 1];
    float4 acc = make_float4(0.f, 0.f, 0.f, 0.f);
    for (int p = b; p < e2; p++) {
        float4 h = *(const float4*)&g_kout[(size_t)p * OUTD + (lane << 2)];
        acc.x += h.x; acc.y += h.y; acc.z += h.z; acc.w += h.w;
    }
    *(float4*)&g_kf[(size_t)v * OUTD + (lane << 2)] = acc;
}

// =====================================================================
// Node GEMM via mma.bf16 3-pass, A and B pre-packed fragment streams.
// =====================================================================
__global__ __launch_bounds__(256)
void mma_gemm(const uint32_t* __restrict__ As, const uint32_t* __restrict__ Bs,
              int Kchunks, int Ntot,
              const float* __restrict__ bias,
              const float* __restrict__ lng, const float* __restrict__ lnb,
              float* __restrict__ out, int V) {
    __shared__ uint32_t sa[4096];
    __shared__ uint32_t sb[4096];
    __shared__ float red[2][64][2];

    int t = threadIdx.x;
    int lane = t & 31, w = t >> 5;
    int wm = w & 3, wn = w >> 2;
    int row0 = blockIdx.x * 64;
    int nb = blockIdx.y * 128;

    float acc[8][4];
    #pragma unroll
    for (int j = 0; j < 8; j++) { acc[j][0]=acc[j][1]=acc[j][2]=acc[j][3]=0.f; }

    const uint4* asrc = (const uint4*)(As + (((size_t)blockIdx.x * Kchunks) << 12));
    const uint4* bsrc = (const uint4*)(Bs + (((size_t)blockIdx.y * Kchunks) << 12));

    for (int c = 0; c < Kchunks; c++) {
        __syncthreads();
        #pragma unroll
        for (int i = 0; i < 4; i++) {
            ((uint4*)sa)[t + (i << 8)] = asrc[(c << 10) + t + (i << 8)];
            ((uint4*)sb)[t + (i << 8)] = bsrc[(c << 10) + t + (i << 8)];
        }
        __syncthreads();
        #pragma unroll
        for (int ks = 0; ks < 2; ks++) {
            uint4 ah = ((const uint4*)sa)[(wm * 2 + ks) * 32 + lane];
            uint4 al = ((const uint4*)sa)[512 + (wm * 2 + ks) * 32 + lane];
            #pragma unroll
            for (int j = 0; j < 8; j++) {
                int nt = wn * 8 + j;
                uint2 bh = ((const uint2*)sb)[(nt * 2 + ks) * 32 + lane];
                uint2 bl = ((const uint2*)sb)[1024 + (nt * 2 + ks) * 32 + lane];
                MMA_BF16(acc[j], ah, bh);
                MMA_BF16(acc[j], ah, bl);
                MMA_BF16(acc[j], al, bh);
            }
        }
    }

    int rl = row0 + wm * 16 + (lane >> 2);
    int rh = rl + 8;
    #pragma unroll
    for (int j = 0; j < 8; j++) {
        int gc = nb + wn * 64 + j * 8 + ((lane & 3) << 1);
        float b0 = bias[gc], b1 = bias[gc + 1];
        acc[j][0] += b0; acc[j][1] += b1; acc[j][2] += b0; acc[j][3] += b1;
    }
    if (lng == nullptr) {
        #pragma unroll
        for (int j = 0; j < 8; j++) {
            int gc = nb + wn * 64 + j * 8 + ((lane & 3) << 1);
            if (rl < V) *(float2*)&out[(size_t)rl * Ntot + gc] = make_float2(acc[j][0], acc[j][1]);
            if (rh < V) *(float2*)&out[(size_t)rh * Ntot + gc] = make_float2(acc[j][2], acc[j][3]);
        }
    } else {
        float s_lo=0.f, q_lo=0.f, s_hi=0.f, q_hi=0.f;
        #pragma unroll
        for (int j = 0; j < 8; j++) {
            s_lo += acc[j][0] + acc[j][1];
            q_lo += acc[j][0]*acc[j][0] + acc[j][1]*acc[j][1];
            s_hi += acc[j][2] + acc[j][3];
            q_hi += acc[j][2]*acc[j][2] + acc[j][3]*acc[j][3];
        }
        #pragma unroll
        for (int m = 1; m <= 2; m <<= 1) {
            s_lo += __shfl_xor_sync(0xffffffffu, s_lo, m);
            q_lo += __shfl_xor_sync(0xffffffffu, q_lo, m);
            s_hi += __shfl_xor_sync(0xffffffffu, s_hi, m);
            q_hi += __shfl_xor_sync(0xffffffffu, q_hi, m);
        }
        int rloc = wm * 16 + (lane >> 2);
        if ((lane & 3) == 0) {
            red[wn][rloc][0] = s_lo;   red[wn][rloc][1] = q_lo;
            red[wn][rloc+8][0] = s_hi; red[wn][rloc+8][1] = q_hi;
        }
        __syncthreads();
        float ts_lo = s_lo + red[wn ^ 1][rloc][0];
        float tq_lo = q_lo + red[wn ^ 1][rloc][1];
        float ts_hi = s_hi + red[wn ^ 1][rloc + 8][0];
        float tq_hi = q_hi + red[wn ^ 1][rloc + 8][1];
        float mu_lo = ts_lo * (1.f/128.f);
        float mu_hi = ts_hi * (1.f/128.f);
        float rs_lo = rsqrtf(tq_lo * (1.f/128.f) - mu_lo*mu_lo + EPS);
        float rs_hi = rsqrtf(tq_hi * (1.f/128.f) - mu_hi*mu_hi + EPS);
        #pragma unroll
        for (int j = 0; j < 8; j++) {
            int gc = wn * 64 + j * 8 + ((lane & 3) << 1);
            float g0 = lng[gc], g1 = lng[gc+1];
            float bb0 = lnb[gc], bb1 = lnb[gc+1];
            if (rl < V) {
                float o0 = fmaxf((acc[j][0]-mu_lo)*rs_lo*g0 + bb0, 0.f);
                float o1 = fmaxf((acc[j][1]-mu_lo)*rs_lo*g1 + bb1, 0.f);
                *(float2*)&out[(size_t)rl * 128 + gc] = make_float2(o0, o1);
            }
            if (rh < V) {
                float o2 = fmaxf((acc[j][2]-mu_hi)*rs_hi*g0 + bb0, 0.f);
                float o3 = fmaxf((acc[j][3]-mu_hi)*rs_hi*g1 + bb1, 0.f);
                *(float2*)&out[(size_t)rh * 128 + gc] = make_float2(o2, o3);
            }
        }
    }
}

// =====================================================================
// Kron edge GEMM, edges in SORTED (perm) order; stores LN'd rows to g_kout.
// M=128 edges x N=128 outs, K=400 (5 chunks of 80).
// =====================================================================
__global__ __launch_bounds__(256, 2)
void kron_mma(const int* __restrict__ src,
              const uint32_t* __restrict__ Wk2S,
              const float* __restrict__ bk2,
              const float* __restrict__ lng, const float* __restrict__ lnb,
              int E) {
    extern __shared__ uint32_t dsm[];
    uint32_t* sa = dsm;                  // 10240
    uint32_t* sb = dsm + 10240;          // 10240
    float* Ss = (float*)(dsm + 20480);   // 128*20
    float* Ds = Ss + 2560;               // 128*20
    __shared__ int ssrc[128], sdste[128];
    __shared__ float red[2][128][2];

    int t = threadIdx.x;
    int lane = t & 31, w = t >> 5;
    int wm = w & 3, wn = w >> 2;
    int e0 = blockIdx.x * 128;

    if (t < 128) {
        int pp = e0 + t; if (pp >= E) pp = E - 1;
        int oe = g_perm[pp];              // original edge id
        ssrc[t] = src[oe];
        sdste[t] = oe;
    }
    __syncthreads();
    for (int idx = t; idx < 640; idx += 256) {
        int e = idx / 5, q = idx - e * 5;
        ((float4*)Ss)[idx] = *(const float4*)&g_npj[ssrc[e] * KP + q * 4];
        // dst of original edge oe:
        // npj[dst] gather — we stored oe; dst lookup via global dst array not
        // passed; instead we precompute npjD pointer outside? see note below.
        (void)sdste;
        ((float4*)Ds)[idx] = make_float4(0.f, 0.f, 0.f, 0.f);
    }
    __syncthreads();
    // proper Ds fill (needs dst): done via second arg path below
    // (replaced at call site by passing dst-gathered indices in ssrc2)
    // -- implemented directly here using g_dstidx --
    // placeholder removed
    float acc[2][8][4];
    #pragma unroll
    for (int r = 0; r < 2; r++)
        #pragma unroll
        for (int j = 0; j < 8; j++) { acc[r][j][0]=acc[r][j][1]=acc[r][j][2]=acc[r][j][3]=0.f; }

    (void)acc;
    // NOTE: real implementation below in kron_mma2
}

// Actual kron kernel (takes dst too).
__global__ __launch_bounds__(256, 2)
void kron_mma2(const int* __restrict__ src, const int* __restrict__ dst,
               const uint32_t* __restrict__ Wk2S,
               const float* __restrict__ bk2,
               const float* __restrict__ lng, const float* __restrict__ lnb,
               int E) {
    extern __shared__ uint32_t dsm[];
    uint32_t* sa = dsm;                  // 10240: hi [0,5120) lo [5120,10240)
    uint32_t* sb = dsm + 10240;          // 10240
    float* Ss = (float*)(dsm + 20480);   // 128*20
    float* Ds = Ss + 2560;               // 128*20
    __shared__ int ssrc[128], sdst[128];
    __shared__ float red[2][128][2];

    int t = threadIdx.x;
    int lane = t & 31, w = t >> 5;
    int wm = w & 3, wn = w >> 2;
    int e0 = blockIdx.x * 128;

    if (t < 128) {
        int pp = e0 + t; if (pp >= E) pp = E - 1;
        int oe = g_perm[pp];
        ssrc[t] = src[oe];
        sdst[t] = dst[oe];
    }
    __syncthreads();
    for (int idx = t; idx < 640; idx += 256) {
        int e = idx / 5, q = idx - e * 5;
        ((float4*)Ss)[idx] = *(const float4*)&g_npj[ssrc[e] * KP + q * 4];
        ((float4*)Ds)[idx] = *(const float4*)&g_npj[sdst[e] * KP + q * 4];
    }

    float acc[2][8][4];
    #pragma unroll
    for (int r = 0; r < 2; r++)
        #pragma unroll
        for (int j = 0; j < 8; j++) { acc[r][j][0]=acc[r][j][1]=acc[r][j][2]=acc[r][j][3]=0.f; }

    int be = t >> 1, ih = t & 1;
    int amt = be >> 4;
    int ribase = (be >> 3) & 1;
    int alnb = (be & 7) << 2;

    for (int c = 0; c < 5; c++) {
        __syncthreads();
        {
            const float* ds = &Ds[be * 20];
            #pragma unroll
            for (int iv = 0; iv < 2; iv++) {
                int il = ih * 2 + iv;
                float sv = Ss[be * 20 + c * 4 + il];
                #pragma unroll
                for (int q = 0; q < 10; q++) {
                    float2 d = *(const float2*)&ds[2 * q];
                    float p0 = sv * d.x, p1 = sv * d.y;
                    int kp = il * 10 + q;
                    int ai = (((amt * 5 + (kp >> 3)) * 32 + alnb + (kp & 3)) << 2)
                             + ribase + (((kp >> 2) & 1) << 1);
                    uint32_t hi, lo;
                    split_pair(p0, p1, hi, lo);
                    sa[ai] = hi;
                    sa[5120 + ai] = lo;
                }
            }
        }
        {
            const uint4* bsrc = (const uint4*)(Wk2S + c * 10240);
            #pragma unroll
            for (int i = 0; i < 10; i++)
                ((uint4*)sb)[t + (i << 8)] = bsrc[t + (i << 8)];
        }
        __syncthreads();
        #pragma unroll
        for (int ks = 0; ks < 5; ks++) {
            uint4 ah0 = ((const uint4*)sa)[((wm * 2 + 0) * 5 + ks) * 32 + lane];
            uint4 al0 = ((const uint4*)sa)[1280 + ((wm * 2 + 0) * 5 + ks) * 32 + lane];
            uint4 ah1 = ((const uint4*)sa)[((wm * 2 + 1) * 5 + ks) * 32 + lane];
            uint4 al1 = ((const uint4*)sa)[1280 + ((wm * 2 + 1) * 5 + ks) * 32 + lane];
            #pragma unroll
            for (int j = 0; j < 8; j++) {
                int nt = wn * 8 + j;
                uint2 bh = ((const uint2*)sb)[(nt * 5 + ks) * 32 + lane];
                uint2 bl = ((const uint2*)sb)[2560 + (nt * 5 + ks) * 32 + lane];
                MMA_BF16(acc[0][j], ah0, bh);
                MMA_BF16(acc[0][j], ah0, bl);
                MMA_BF16(acc[0][j], al0, bh);
                MMA_BF16(acc[1][j], ah1, bh);
                MMA_BF16(acc[1][j], ah1, bl);
                MMA_BF16(acc[1][j], al1, bh);
            }
        }
    }

    // ---- epilogue: bias + LN(128) + relu + coalesced store to g_kout ----
    #pragma unroll
    for (int r = 0; r < 2; r++)
        #pragma unroll
        for (int j = 0; j < 8; j++) {
            int gc = wn * 64 + j * 8 + ((lane & 3) << 1);
            float b0 = bk2[gc], b1 = bk2[gc + 1];
            acc[r][j][0] += b0; acc[r][j][1] += b1;
            acc[r][j][2] += b0; acc[r][j][3] += b1;
        }
    float sum[2][2], sq[2][2];
    #pragma unroll
    for (int r = 0; r < 2; r++) {
        float s_lo=0.f, q_lo=0.f, s_hi=0.f, q_hi=0.f;
        #pragma unroll
        for (int j = 0; j < 8; j++) {
            s_lo += acc[r][j][0] + acc[r][j][1];
            q_lo += acc[r][j][0]*acc[r][j][0] + acc[r][j][1]*acc[r][j][1];
            s_hi += acc[r][j][2] + acc[r][j][3];
            q_hi += acc[r][j][2]*acc[r][j][2] + acc[r][j][3]*acc[r][j][3];
        }
        #pragma unroll
        for (int m = 1; m <= 2; m <<= 1) {
            s_lo += __shfl_xor_sync(0xffffffffu, s_lo, m);
            q_lo += __shfl_xor_sync(0xffffffffu, q_lo, m);
            s_hi += __shfl_xor_sync(0xffffffffu, s_hi, m);
            q_hi += __shfl_xor_sync(0xffffffffu, q_hi, m);
        }
        sum[r][0] = s_lo; sq[r][0] = q_lo;
        sum[r][1] = s_hi; sq[r][1] = q_hi;
        if ((lane & 3) == 0) {
            int rloc = wm * 32 + r * 16 + (lane >> 2);
            red[wn][rloc][0] = s_lo;     red[wn][rloc][1] = q_lo;
            red[wn][rloc + 8][0] = s_hi; red[wn][rloc + 8][1] = q_hi;
        }
    }
    __syncthreads();
    #pragma unroll
    for (int r = 0; r < 2; r++) {
        #pragma unroll
        for (int h = 0; h < 2; h++) {
            int rloc = wm * 32 + r * 16 + h * 8 + (lane >> 2);
            float ts = sum[r][h] + red[wn ^ 1][rloc][0];
            float tq = sq[r][h] + red[wn ^ 1][rloc][1];
            float mu = ts * (1.f / 128.f);
            float rs = rsqrtf(tq * (1.f / 128.f) - mu * mu + EPS);
            int gp = e0 + rloc;                // sorted position
            if (gp < E) {
                float* p = &g_kout[(size_t)gp * OUTD];
                #pragma unroll
                for (int j = 0; j < 8; j++) {
                    int gc = wn * 64 + j * 8 + ((lane & 3) << 1);
                    float g0 = lng[gc], g1 = lng[gc + 1];
                    float bb0 = lnb[gc], bb1 = lnb[gc + 1];
                    float o0 = fmaxf((acc[r][j][2*h  ]-mu)*rs*g0 + bb0, 0.f);
                    float o1 = fmaxf((acc[r][j][2*h+1]-mu)*rs*g1 + bb1, 0.f);
                    *(float2*)&p[gc] = make_float2(o0, o1);
                }
            }
        }
    }
}

// ---------------- GRU gates + relu + LN ----------------
__global__ void gates_kernel(const float* __restrict__ x,
                             const float* __restrict__ lng,
                             const float* __restrict__ lnb, int V) {
    int v = blockIdx.x * 4 + (threadIdx.x >> 5);
    if (v >= V) return;
    int lane = threadIdx.x & 31;
    const float* gi = &g_gi[(size_t)v * 384];
    const float* gh = &g_gh[(size_t)v * 384];
    float4 gir = *(const float4*)&gi[(lane << 2)];
    float4 giz = *(const float4*)&gi[128 + (lane << 2)];
    float4 gin = *(const float4*)&gi[256 + (lane << 2)];
    float4 ghr = *(const float4*)&gh[(lane << 2)];
    float4 ghz = *(const float4*)&gh[128 + (lane << 2)];
    float4 ghn = *(const float4*)&gh[256 + (lane << 2)];
    float4 xv  = *(const float4*)&x[(size_t)v * D + (lane << 2)];
    float h[4];
    #pragma unroll
    for (int i = 0; i < 4; i++) {
        float a_r = (&gir.x)[i] + (&ghr.x)[i];
        float a_z = (&giz.x)[i] + (&ghz.x)[i];
        float r = 1.f / (1.f + expf(-a_r));
        float z = 1.f / (1.f + expf(-a_z));
        float n = tanhf((&gin.x)[i] + r * (&ghn.x)[i]);
        float hh = (1.f - z) * n + z * (&xv.x)[i];
        h[i] = fmaxf(hh, 0.f);
    }
    float s = h[0] + h[1] + h[2] + h[3];
    #pragma unroll
    for (int m = 16; m; m >>= 1) s += __shfl_xor_sync(0xffffffffu, s, m);
    float mu = s * (1.f / 128.f);
    float q = 0.f;
    #pragma unroll
    for (int i = 0; i < 4; i++) { float d0 = h[i] - mu; q = fmaf(d0, d0, q); }
    #pragma unroll
    for (int m = 16; m; m >>= 1) q += __shfl_xor_sync(0xffffffffu, q, m);
    float rstd = rsqrtf(q * (1.f / 128.f) + EPS);
    float4 gv = *(const float4*)&lng[lane << 2];
    float4 b2 = *(const float4*)&lnb[lane << 2];
    float4 o;
    o.x = (h[0] - mu) * rstd * gv.x + b2.x;
    o.y = (h[1] - mu) * rstd * gv.y + b2.y;
    o.z = (h[2] - mu) * rstd * gv.z + b2.z;
    o.w = (h[3] - mu) * rstd * gv.w + b2.w;
    *(float4*)&g_gru[(size_t)v * D + (lane << 2)] = o;
}

// ---------------- host ----------------
extern "C" void kernel_launch(void* const* d_in, const int* in_sizes, int n_in,
                              void* d_out, int out_size) {
    const float* node   = (const float*)d_in[0];
    const int*   src    = (const int*)  d_in[1];
    const int*   dst    = (const int*)  d_in[2];
    const float* W_edge = (const float*)d_in[3];
    const float* b_edge = (const float*)d_in[4];
    const float* W_pn   = (const float*)d_in[5];
    const float* b_pn   = (const float*)d_in[6];
    const float* W_ih   = (const float*)d_in[7];
    const float* b_ih   = (const float*)d_in[8];
    const float* W_hh   = (const float*)d_in[9];
    const float* b_hh   = (const float*)d_in[10];
    const float* ln_g   = (const float*)d_in[11];
    const float* ln_b   = (const float*)d_in[12];
    const float* Wk1    = (const float*)d_in[13];
    const float* bk1    = (const float*)d_in[14];
    const float* lnk1_g = (const float*)d_in[15];
    const float* lnk1_b = (const float*)d_in[16];
    const float* Wk2    = (const float*)d_in[17];
    const float* bk2    = (const float*)d_in[18];
    const float* lnk2_g = (const float*)d_in[19];
    const float* lnk2_b = (const float*)d_in[20];
    const float* Wc     = (const float*)d_in[21];
    const float* bc     = (const float*)d_in[22];
    const float* lnc_g  = (const float*)d_in[23];
    const float* lnc_b  = (const float*)d_in[24];
    int V = in_sizes[0] / D;
    int E = in_sizes[1];
    float* out = (float*)d_out;

    float *p_asum, *p_lmax, *p_hv, *p_ctx, *p_kf, *p_gi, *p_gh, *p_gru;
    int *p_cnt, *p_cnt2;
    uint32_t *p_WpnS, *p_WihS, *p_WhhS, *p_WcS, *p_Wk2S;
    uint32_t *p_Anode, *p_Actx, *p_Acat;
    cudaGetSymbolAddress((void**)&p_asum,  g_asum);
    cudaGetSymbolAddress((void**)&p_lmax,  g_lmax);
    cudaGetSymbolAddress((void**)&p_hv,    g_hv);
    cudaGetSymbolAddress((void**)&p_ctx,   g_ctx);
    cudaGetSymbolAddress((void**)&p_kf,    g_kf);
    cudaGetSymbolAddress((void**)&p_gi,    g_gi);
    cudaGetSymbolAddress((void**)&p_gh,    g_gh);
    cudaGetSymbolAddress((void**)&p_gru,   g_gru);
    cudaGetSymbolAddress((void**)&p_cnt,   g_cnt);
    cudaGetSymbolAddress((void**)&p_cnt2,  g_cnt2);
    cudaGetSymbolAddress((void**)&p_WpnS,  g_WpnS);
    cudaGetSymbolAddress((void**)&p_WihS,  g_WihS);
    cudaGetSymbolAddress((void**)&p_WhhS,  g_WhhS);
    cudaGetSymbolAddress((void**)&p_WcS,   g_WcS);
    cudaGetSymbolAddress((void**)&p_Wk2S,  g_Wk2S);
    cudaGetSymbolAddress((void**)&p_Anode, g_Anode);
    cudaGetSymbolAddress((void**)&p_Actx,  g_Actx);
    cudaGetSymbolAddress((void**)&p_Acat,  g_Acat);

    static bool attr_set = false;
    if (!attr_set) {
        cudaFuncSetAttribute(kron_mma2, cudaFuncAttributeMaxDynamicSharedMemorySize, 103000);
        attr_set = true;
    }

    int NBv = (V + 63) / 64;

    // zero small accumulators + sort counters
    {
        int n4 = V / 4;
        zero_kernel<<<(n4 + 255) / 256, 256>>>((float4*)p_asum, n4);
        zero_kernel<<<(n4 + 255) / 256, 256>>>((float4*)p_lmax, n4);
        zeroi_kernel<<<(V + 255) / 256, 256>>>(p_cnt, V);
        zeroi_kernel<<<(V + 255) / 256, 256>>>(p_cnt2, V);
    }

    // CSR build
    hist_kernel<<<(E + 255) / 256, 256>>>(dst, E);
    scan_kernel<<<1, 1024>>>(V, E);
    scatter_kernel<<<(E + 255) / 256, 256>>>(dst, E);

    // pack weights
    pack_w_frag<<<(64 * 128 + 255) / 256, 256>>>(W_pn, 128, 128, 0, p_WpnS);
    pack_w_frag<<<(64 * 384 + 255) / 256, 256>>>(W_ih, 128, 384, 1, p_WihS);
    pack_w_frag<<<(64 * 384 + 255) / 256, 256>>>(W_hh, 128, 384, 1, p_WhhS);
    pack_w_frag<<<(128 * 128 + 255) / 256, 256>>>(Wc, 256, 128, 0, p_WcS);
    pack_wk2<<<(200 * 128 + 255) / 256, 256>>>(Wk2, p_Wk2S);

    // pack node activations
    pack_act<<<NBv, 256>>>(node, 128, nullptr, 0, 0, p_Anode, V);

    npj_kernel<<<(V + 3) / 4, 128>>>(node, Wk1, bk1, lnk1_g, lnk1_b, V);
    logits_kernel<<<(E + 3) / 4, 128>>>(node, src, dst, W_edge, b_edge, E);
    expsum_kernel<<<(E + 255) / 256, 256>>>(dst, E);

    // hv = node @ W_pn + b_pn
    mma_gemm<<<dim3(NBv, 1), 256>>>(p_Anode, p_WpnS, 4, 128,
                                    b_pn, nullptr, nullptr, p_hv, V);

    // edge kron GEMM (sorted order) -> g_kout rows
    kron_mma2<<<(E + 127) / 128, 256, 102400>>>(src, dst, p_Wk2S,
                                                bk2, lnk2_g, lnk2_b, E);

    // kf[v] = sum of its sorted kout rows (sequential reads)
    kf_csr<<<(V + 7) / 8, 256>>>(V);

    // ctx[v] = relu(sum hv[src]*a/asum) via CSR (no atomics)
    ctx_csr<<<(V + 7) / 8, 256>>>(src, V);

    // pack ctx (relu already applied)
    pack_act<<<NBv, 256>>>(p_ctx, 128, nullptr, 0, 0, p_Actx, V);

    // gi / gh GEMMs
    mma_gemm<<<dim3(NBv, 3), 256>>>(p_Actx, p_WihS, 4, 384,
                                    b_ih, nullptr, nullptr, p_gi, V);
    mma_gemm<<<dim3(NBv, 3), 256>>>(p_Anode, p_WhhS, 4, 384,
                                    b_hh, nullptr, nullptr, p_gh, V);

    gates_kernel<<<(V + 3) / 4, 128>>>(node, ln_g, ln_b, V);

    // pack cat(gru, kf)
    pack_act<<<NBv, 256>>>(p_gru, 128, p_kf, 128, 0, p_Acat, V);

    // out = relu(LN(cat @ Wc + bc))
    mma_gemm<<<dim3(NBv, 1), 256>>>(p_Acat, p_WcS, 8, 128,
                                    bc, lnc_g, lnc_b, out, V);
}

// round 5
// speedup vs baseline: 1.0009x; 1.0009x over previous
#include <cuda_runtime.h>
#include <cuda_bf16.h>
#include <math.h>
#include <stdint.h>

#define D     128
#define KP    20
#define OUTD  128
#define VMAX  100000
#define EMAX  400000
#define EPS   1e-5f
#define NBMAX 1563   // (VMAX+63)/64

// ---------------- scratch (device globals; no allocations) ----------------
__device__ float g_npj  [VMAX * KP];
__device__ float g_logit[EMAX];
__device__ float g_aexp [EMAX];
__device__ float g_lmax [VMAX];
__device__ float g_asum [VMAX];
__device__ float g_hv   [VMAX * D];
__device__ float g_ctx  [VMAX * D];
__device__ float g_kf   [VMAX * OUTD];
__device__ float g_gi   [VMAX * 3 * D];
__device__ float g_gh   [VMAX * 3 * D];
__device__ float g_gru  [VMAX * D];
__device__ float g_kout [(size_t)EMAX * OUTD];   // per-edge kron rows (sorted order)

// CSR sort scratch
__device__ int g_cnt [VMAX];
__device__ int g_cnt2[VMAX];
__device__ int g_row [VMAX + 1];
__device__ int g_perm[EMAX];

// fragment-ordered bf16 hi/lo weight streams
__device__ uint32_t g_WpnS[1 * 4 * 4096];
__device__ uint32_t g_WihS[3 * 4 * 4096];
__device__ uint32_t g_WhhS[3 * 4 * 4096];
__device__ uint32_t g_WcS [1 * 8 * 4096];
__device__ uint32_t g_Wk2S[5 * 10240];

// fragment-ordered bf16 hi/lo activation streams
__device__ uint32_t g_Anode[(size_t)NBMAX * 4 * 4096];
__device__ uint32_t g_Actx [(size_t)NBMAX * 4 * 4096];
__device__ uint32_t g_Acat [(size_t)NBMAX * 8 * 4096];

// ---------------- fast bf16 hi/lo split (truncation) ----------------
__device__ __forceinline__ void split_pair(float a0, float a1,
                                           uint32_t& hi, uint32_t& lo) {
    uint32_t b0 = __float_as_uint(a0), b1 = __float_as_uint(a1);
    uint32_t hp;
    asm("prmt.b32 %0, %1, %2, 0x7632;" : "=r"(hp) : "r"(b0), "r"(b1));
    float l0 = a0 - __uint_as_float(b0 & 0xffff0000u);
    float l1 = a1 - __uint_as_float(b1 & 0xffff0000u);
    __nv_bfloat162 lp = __floats2bfloat162_rn(l0, l1);
    hi = hp;
    lo = *(uint32_t*)&lp;
}

#define MMA_BF16(c, A, B) asm volatile( \
    "mma.sync.aligned.m16n8k16.row.col.f32.bf16.bf16.f32 " \
    "{%0,%1,%2,%3}, {%4,%5,%6,%7}, {%8,%9}, {%0,%1,%2,%3};\n" \
    : "+f"(c[0]), "+f"(c[1]), "+f"(c[2]), "+f"(c[3]) \
    : "r"(A.x), "r"(A.y), "r"(A.z), "r"(A.w), "r"(B.x), "r"(B.y))

// ---------------- utility kernels ----------------
__global__ void zero_kernel(float4* p, int n4) {
    int i = blockIdx.x * blockDim.x + threadIdx.x;
    if (i < n4) p[i] = make_float4(0.f, 0.f, 0.f, 0.f);
}
__global__ void zeroi_kernel(int* p, int n) {
    int i = blockIdx.x * blockDim.x + threadIdx.x;
    if (i < n) p[i] = 0;
}

// ---------------- CSR build: hist -> scan -> scatter ----------------
__global__ void hist_kernel(const int* __restrict__ dst, int E) {
    int e = blockIdx.x * blockDim.x + threadIdx.x;
    if (e < E) atomicAdd(&g_cnt[dst[e]], 1);
}
__global__ void scan_kernel(int V, int E) {
    __shared__ int sums[1024];
    int t = threadIdx.x;
    int chunk = (V + 1023) >> 10;
    int lo = t * chunk, hi = lo + chunk; if (hi > V) hi = V; if (lo > V) lo = V;
    int s = 0;
    for (int i = lo; i < hi; i++) s += g_cnt[i];
    sums[t] = s;
    __syncthreads();
    for (int off = 1; off < 1024; off <<= 1) {
        int v = (t >= off) ? sums[t - off] : 0;
        __syncthreads();
        sums[t] += v;
        __syncthreads();
    }
    int base = (t == 0) ? 0 : sums[t - 1];
    for (int i = lo; i < hi; i++) { int c = g_cnt[i]; g_row[i] = base; base += c; }
    if (t == 0) g_row[V] = E;
}
__global__ void scatter_kernel(const int* __restrict__ dst, int E) {
    int e = blockIdx.x * blockDim.x + threadIdx.x;
    if (e >= E) return;
    int d = dst[e];
    int pos = g_row[d] + atomicAdd(&g_cnt2[d], 1);
    g_perm[pos] = e;
}

// pack weights into fragment stream
__global__ void pack_w_frag(const float* __restrict__ W, int K, int Ntot,
                            int transp, uint32_t* __restrict__ out) {
    int idx = blockIdx.x * blockDim.x + threadIdx.x;
    int total = (K / 2) * Ntot;
    if (idx >= total) return;
    int kp = idx / Ntot, n = idx - kp * Ntot;
    int k0 = 2 * kp;
    float w0, w1;
    if (transp) { w0 = W[n * K + k0]; w1 = W[n * K + k0 + 1]; }
    else        { w0 = W[k0 * Ntot + n]; w1 = W[(k0 + 1) * Ntot + n]; }
    int c = kp >> 4, kpl = kp & 15;
    int ny = n >> 7, nl = n & 127;
    int bi = ((((nl >> 3) * 2 + (kpl >> 3)) * 32 + ((nl & 7) << 2) + (kpl & 3)) << 1)
             + ((kpl >> 2) & 1);
    size_t base = ((size_t)(ny * (K >> 5) + c)) << 12;
    uint32_t hi, lo;
    split_pair(w0, w1, hi, lo);
    out[base + bi] = hi;
    out[base + 2048 + bi] = lo;
}

// Wk2 [400][128] -> kron stream
__global__ void pack_wk2(const float* __restrict__ W, uint32_t* __restrict__ out) {
    int idx = blockIdx.x * blockDim.x + threadIdx.x;
    if (idx >= 200 * 128) return;
    int kp = idx >> 7, n = idx & 127;
    float w0 = W[(2 * kp) * 128 + n];
    float w1 = W[(2 * kp + 1) * 128 + n];
    int c = kp / 40, kpl = kp - c * 40;
    int bi = ((((n >> 3) * 5 + (kpl >> 3)) * 32 + ((n & 7) << 2) + (kpl & 3)) << 1)
             + ((kpl >> 2) & 1);
    uint32_t hi, lo;
    split_pair(w0, w1, hi, lo);
    out[c * 10240 + bi] = hi;
    out[c * 10240 + 5120 + bi] = lo;
}

// pack fp32 activation into fragment stream
__global__ void pack_act(const float* __restrict__ X0, int K0,
                         const float* __restrict__ X1, int K1, int relu,
                         uint32_t* __restrict__ out, int V) {
    int t = threadIdx.x;
    int mb = blockIdx.x;
    int K = K0 + K1;
    int Kch = K >> 5;
    size_t obase = ((size_t)mb * Kch) << 12;
    for (int it = 0; it < Kch * 8; it++) {
        int c = it >> 3;
        int idx = ((it & 7) << 8) + t;
        int ri = idx & 3;
        int lane = (idx >> 2) & 31;
        int kstep = (idx >> 7) & 1;
        int mt = idx >> 8;
        int row = mb * 64 + mt * 16 + (ri & 1) * 8 + (lane >> 2);
        if (row >= V) row = V - 1;
        int kp = kstep * 8 + ((ri >> 1) << 2) + (lane & 3);
        int k = c * 32 + kp * 2;
        float2 a;
        if (k < K0) a = *(const float2*)&X0[(size_t)row * K0 + k];
        else        a = *(const float2*)&X1[(size_t)row * K1 + (k - K0)];
        if (relu) { a.x = fmaxf(a.x, 0.f); a.y = fmaxf(a.y, 0.f); }
        uint32_t hi, lo;
        split_pair(a.x, a.y, hi, lo);
        size_t base = obase + ((size_t)c << 12);
        out[base + idx] = hi;
        out[base + 2048 + idx] = lo;
    }
}

// ---------------- npj ----------------
__global__ void npj_kernel(const float* __restrict__ x,
                           const float* __restrict__ Wk1,
                           const float* __restrict__ bk1,
                           const float* __restrict__ g,
                           const float* __restrict__ b, int V) {
    __shared__ float xs[4][D];
    int warp = threadIdx.x >> 5, lane = threadIdx.x & 31;
    int v  = blockIdx.x * 4 + warp;
    int vc = v < V ? v : V - 1;
    *(float4*)&xs[warp][lane << 2] = *(const float4*)&x[vc * D + (lane << 2)];
    __syncwarp();
    float y = 0.f;
    if (lane < KP) {
        #pragma unroll 8
        for (int k = 0; k < D; k++) y = fmaf(xs[warp][k], Wk1[k * KP + lane], y);
        y += bk1[lane];
    }
    float s = (lane < KP) ? y : 0.f;
    #pragma unroll
    for (int m = 16; m; m >>= 1) s += __shfl_xor_sync(0xffffffffu, s, m);
    float mu = s * (1.f / KP);
    float dv = (lane < KP) ? (y - mu) * (y - mu) : 0.f;
    #pragma unroll
    for (int m = 16; m; m >>= 1) dv += __shfl_xor_sync(0xffffffffu, dv, m);
    float rstd = rsqrtf(dv * (1.f / KP) + EPS);
    if (v < V && lane < KP) {
        float val = (y - mu) * rstd * g[lane] + b[lane];
        g_npj[v * KP + lane] = fmaxf(val, 0.f);
    }
}

// ---------------- edge logits + segment max ----------------
__global__ void logits_kernel(const float* __restrict__ x,
                              const int* __restrict__ src,
                              const int* __restrict__ dst,
                              const float* __restrict__ We,
                              const float* __restrict__ be, int E) {
    int e = blockIdx.x * 4 + (threadIdx.x >> 5);
    if (e >= E) return;
    int lane = threadIdx.x & 31;
    int sn = src[e], dn = dst[e];
    float4 xd = *(const float4*)&x[dn * D + (lane << 2)];
    float4 w1 = *(const float4*)&We[lane << 2];
    float4 xv = *(const float4*)&x[sn * D + (lane << 2)];
    float4 w2 = *(const float4*)&We[D + (lane << 2)];
    float p = xd.x * w1.x + xd.y * w1.y + xd.z * w1.z + xd.w * w1.w
            + xv.x * w2.x + xv.y * w2.y + xv.z * w2.z + xv.w * w2.w;
    #pragma unroll
    for (int m = 16; m; m >>= 1) p += __shfl_xor_sync(0xffffffffu, p, m);
    if (lane == 0) {
        float lg = fmaxf(p + be[0], 0.f);
        g_logit[e] = lg;
        atomicMax((int*)&g_lmax[dn], __float_as_int(lg));  // valid: lg >= 0
    }
}

__global__ void expsum_kernel(const int* __restrict__ dst, int E) {
    int e = blockIdx.x * blockDim.x + threadIdx.x;
    if (e >= E) return;
    int dn = dst[e];
    float a = expf(g_logit[e] - g_lmax[dn]);
    g_aexp[e] = a;
    atomicAdd(&g_asum[dn], a);
}

// ---------------- context via CSR: ctx[v] = relu(sum hv[src[e]]*a/asum) ----
__global__ void ctx_csr(const int* __restrict__ src, int V) {
    int v = blockIdx.x * 8 + (threadIdx.x >> 5);
    if (v >= V) return;
    int lane = threadIdx.x & 31;
    int b = g_row[v], e2 = g_row[v + 1];
    float rinv = (e2 > b) ? (1.f / g_asum[v]) : 0.f;
    float4 acc = make_float4(0.f, 0.f, 0.f, 0.f);
    for (int p = b; p < e2; p++) {
        int pe = g_perm[p];
        float coef = g_aexp[pe] * rinv;
        float4 h = *(const float4*)&g_hv[(size_t)src[pe] * D + (lane << 2)];
        acc.x = fmaf(h.x, coef, acc.x);
        acc.y = fmaf(h.y, coef, acc.y);
        acc.z = fmaf(h.z, coef, acc.z);
        acc.w = fmaf(h.w, coef, acc.w);
    }
    acc.x = fmaxf(acc.x, 0.f); acc.y = fmaxf(acc.y, 0.f);
    acc.z = fmaxf(acc.z, 0.f); acc.w = fmaxf(acc.w, 0.f);
    *(float4*)&g_ctx[(size_t)v * D + (lane << 2)] = acc;
}

// ---------------- kf via CSR: kf[v] = sum of sorted kout rows ----------------
__global__ void kf_csr(int V) {
    int v = blockIdx.x * 8 + (threadIdx.x >> 5);
    if (v >= V) return;
    int lane = threadIdx.x & 31;
    int b = g_row[v], e2 = g_row[v + 1];
    float4 acc = make_float4(0.f, 0.f, 0.f, 0.f);
    for (int p = b; p < e2; p++) {
        float4 h = *(const float4*)&g_kout[(size_t)p * OUTD + (lane << 2)];
        acc.x += h.x; acc.y += h.y; acc.z += h.z; acc.w += h.w;
    }
    *(float4*)&g_kf[(size_t)v * OUTD + (lane << 2)] = acc;
}

// =====================================================================
// Node GEMM via mma.bf16 3-pass, A and B pre-packed fragment streams.
// =====================================================================
__global__ __launch_bounds__(256)
void mma_gemm(const uint32_t* __restrict__ As, const uint32_t* __restrict__ Bs,
              int Kchunks, int Ntot,
              const float* __restrict__ bias,
              const float* __restrict__ lng, const float* __restrict__ lnb,
              float* __restrict__ out, int V) {
    __shared__ uint32_t sa[4096];
    __shared__ uint32_t sb[4096];
    __shared__ float red[2][64][2];

    int t = threadIdx.x;
    int lane = t & 31, w = t >> 5;
    int wm = w & 3, wn = w >> 2;
    int row0 = blockIdx.x * 64;
    int nb = blockIdx.y * 128;

    float acc[8][4];
    #pragma unroll
    for (int j = 0; j < 8; j++) { acc[j][0]=acc[j][1]=acc[j][2]=acc[j][3]=0.f; }

    const uint4* asrc = (const uint4*)(As + (((size_t)blockIdx.x * Kchunks) << 12));
    const uint4* bsrc = (const uint4*)(Bs + (((size_t)blockIdx.y * Kchunks) << 12));

    for (int c = 0; c < Kchunks; c++) {
        __syncthreads();
        #pragma unroll
        for (int i = 0; i < 4; i++) {
            ((uint4*)sa)[t + (i << 8)] = asrc[(c << 10) + t + (i << 8)];
            ((uint4*)sb)[t + (i << 8)] = bsrc[(c << 10) + t + (i << 8)];
        }
        __syncthreads();
        #pragma unroll
        for (int ks = 0; ks < 2; ks++) {
            uint4 ah = ((const uint4*)sa)[(wm * 2 + ks) * 32 + lane];
            uint4 al = ((const uint4*)sa)[512 + (wm * 2 + ks) * 32 + lane];
            #pragma unroll
            for (int j = 0; j < 8; j++) {
                int nt = wn * 8 + j;
                uint2 bh = ((const uint2*)sb)[(nt * 2 + ks) * 32 + lane];
                uint2 bl = ((const uint2*)sb)[1024 + (nt * 2 + ks) * 32 + lane];
                MMA_BF16(acc[j], ah, bh);
                MMA_BF16(acc[j], ah, bl);
                MMA_BF16(acc[j], al, bh);
            }
        }
    }

    int rl = row0 + wm * 16 + (lane >> 2);
    int rh = rl + 8;
    #pragma unroll
    for (int j = 0; j < 8; j++) {
        int gc = nb + wn * 64 + j * 8 + ((lane & 3) << 1);
        float b0 = bias[gc], b1 = bias[gc + 1];
        acc[j][0] += b0; acc[j][1] += b1; acc[j][2] += b0; acc[j][3] += b1;
    }
    if (lng == nullptr) {
        #pragma unroll
        for (int j = 0; j < 8; j++) {
            int gc = nb + wn * 64 + j * 8 + ((lane & 3) << 1);
            if (rl < V) *(float2*)&out[(size_t)rl * Ntot + gc] = make_float2(acc[j][0], acc[j][1]);
            if (rh < V) *(float2*)&out[(size_t)rh * Ntot + gc] = make_float2(acc[j][2], acc[j][3]);
        }
    } else {
        float s_lo=0.f, q_lo=0.f, s_hi=0.f, q_hi=0.f;
        #pragma unroll
        for (int j = 0; j < 8; j++) {
            s_lo += acc[j][0] + acc[j][1];
            q_lo += acc[j][0]*acc[j][0] + acc[j][1]*acc[j][1];
            s_hi += acc[j][2] + acc[j][3];
            q_hi += acc[j][2]*acc[j][2] + acc[j][3]*acc[j][3];
        }
        #pragma unroll
        for (int m = 1; m <= 2; m <<= 1) {
            s_lo += __shfl_xor_sync(0xffffffffu, s_lo, m);
            q_lo += __shfl_xor_sync(0xffffffffu, q_lo, m);
            s_hi += __shfl_xor_sync(0xffffffffu, s_hi, m);
            q_hi += __shfl_xor_sync(0xffffffffu, q_hi, m);
        }
        int rloc = wm * 16 + (lane >> 2);
        if ((lane & 3) == 0) {
            red[wn][rloc][0] = s_lo;   red[wn][rloc][1] = q_lo;
            red[wn][rloc+8][0] = s_hi; red[wn][rloc+8][1] = q_hi;
        }
        __syncthreads();
        float ts_lo = s_lo + red[wn ^ 1][rloc][0];
        float tq_lo = q_lo + red[wn ^ 1][rloc][1];
        float ts_hi = s_hi + red[wn ^ 1][rloc + 8][0];
        float tq_hi = q_hi + red[wn ^ 1][rloc + 8][1];
        float mu_lo = ts_lo * (1.f/128.f);
        float mu_hi = ts_hi * (1.f/128.f);
        float rs_lo = rsqrtf(tq_lo * (1.f/128.f) - mu_lo*mu_lo + EPS);
        float rs_hi = rsqrtf(tq_hi * (1.f/128.f) - mu_hi*mu_hi + EPS);
        #pragma unroll
        for (int j = 0; j < 8; j++) {
            int gc = wn * 64 + j * 8 + ((lane & 3) << 1);
            float g0 = lng[gc], g1 = lng[gc+1];
            float bb0 = lnb[gc], bb1 = lnb[gc+1];
            if (rl < V) {
                float o0 = fmaxf((acc[j][0]-mu_lo)*rs_lo*g0 + bb0, 0.f);
                float o1 = fmaxf((acc[j][1]-mu_lo)*rs_lo*g1 + bb1, 0.f);
                *(float2*)&out[(size_t)rl * 128 + gc] = make_float2(o0, o1);
            }
            if (rh < V) {
                float o2 = fmaxf((acc[j][2]-mu_hi)*rs_hi*g0 + bb0, 0.f);
                float o3 = fmaxf((acc[j][3]-mu_hi)*rs_hi*g1 + bb1, 0.f);
                *(float2*)&out[(size_t)rh * 128 + gc] = make_float2(o2, o3);
            }
        }
    }
}

// =====================================================================
// Kron edge GEMM, edges in SORTED (perm) order; stores LN'd rows to g_kout.
// M=128 edges x N=128 outs, K=400 (5 chunks of 80).
// =====================================================================
__global__ __launch_bounds__(256, 2)
void kron_mma(const int* __restrict__ src,
              const uint32_t* __restrict__ Wk2S,
              const float* __restrict__ bk2,
              const float* __restrict__ lng, const float* __restrict__ lnb,
              int E) {
    extern __shared__ uint32_t dsm[];
    uint32_t* sa = dsm;                  // 10240
    uint32_t* sb = dsm + 10240;          // 10240
    float* Ss = (float*)(dsm + 20480);   // 128*20
    float* Ds = Ss + 2560;               // 128*20
    __shared__ int ssrc[128], sdste[128];
    __shared__ float red[2][128][2];

    int t = threadIdx.x;
    int lane = t & 31, w = t >> 5;
    int wm = w & 3, wn = w >> 2;
    int e0 = blockIdx.x * 128;

    if (t < 128) {
        int pp = e0 + t; if (pp >= E) pp = E - 1;
        int oe = g_perm[pp];              // original edge id
        ssrc[t] = src[oe];
        sdste[t] = oe;
    }
    __syncthreads();
    for (int idx = t; idx < 640; idx += 256) {
        int e = idx / 5, q = idx - e * 5;
        ((float4*)Ss)[idx] = *(const float4*)&g_npj[ssrc[e] * KP + q * 4];
        // dst of original edge oe:
        // npj[dst] gather — we stored oe; dst lookup via global dst array not
        // passed; instead we precompute npjD pointer outside? see note below.
        (void)sdste;
        ((float4*)Ds)[idx] = make_float4(0.f, 0.f, 0.f, 0.f);
    }
    __syncthreads();
    // proper Ds fill (needs dst): done via second arg path below
    // (replaced at call site by passing dst-gathered indices in ssrc2)
    // -- implemented directly here using g_dstidx --
    // placeholder removed
    float acc[2][8][4];
    #pragma unroll
    for (int r = 0; r < 2; r++)
        #pragma unroll
        for (int j = 0; j < 8; j++) { acc[r][j][0]=acc[r][j][1]=acc[r][j][2]=acc[r][j][3]=0.f; }

    (void)acc;
    // NOTE: real implementation below in kron_mma2
}

// Actual kron kernel (takes dst too).
__global__ __launch_bounds__(256, 2)
void kron_mma2(const int* __restrict__ src, const int* __restrict__ dst,
               const uint32_t* __restrict__ Wk2S,
               const float* __restrict__ bk2,
               const float* __restrict__ lng, const float* __restrict__ lnb,
               int E) {
    extern __shared__ uint32_t dsm[];
    uint32_t* sa = dsm;                  // 10240: hi [0,5120) lo [5120,10240)
    uint32_t* sb = dsm + 10240;          // 10240
    float* Ss = (float*)(dsm + 20480);   // 128*20
    float* Ds = Ss + 2560;               // 128*20
    __shared__ int ssrc[128], sdst[128];
    __shared__ float red[2][128][2];

    int t = threadIdx.x;
    int lane = t & 31, w = t >> 5;
    int wm = w & 3, wn = w >> 2;
    int e0 = blockIdx.x * 128;

    if (t < 128) {
        int pp = e0 + t; if (pp >= E) pp = E - 1;
        int oe = g_perm[pp];
        ssrc[t] = src[oe];
        sdst[t] = dst[oe];
    }
    __syncthreads();
    for (int idx = t; idx < 640; idx += 256) {
        int e = idx / 5, q = idx - e * 5;
        ((float4*)Ss)[idx] = *(const float4*)&g_npj[ssrc[e] * KP + q * 4];
        ((float4*)Ds)[idx] = *(const float4*)&g_npj[sdst[e] * KP + q * 4];
    }

    float acc[2][8][4];
    #pragma unroll
    for (int r = 0; r < 2; r++)
        #pragma unroll
        for (int j = 0; j < 8; j++) { acc[r][j][0]=acc[r][j][1]=acc[r][j][2]=acc[r][j][3]=0.f; }

    int be = t >> 1, ih = t & 1;
    int amt = be >> 4;
    int ribase = (be >> 3) & 1;
    int alnb = (be & 7) << 2;

    for (int c = 0; c < 5; c++) {
        __syncthreads();
        {
            const float* ds = &Ds[be * 20];
            #pragma unroll
            for (int iv = 0; iv < 2; iv++) {
                int il = ih * 2 + iv;
                float sv = Ss[be * 20 + c * 4 + il];
                #pragma unroll
                for (int q = 0; q < 10; q++) {
                    float2 d = *(const float2*)&ds[2 * q];
                    float p0 = sv * d.x, p1 = sv * d.y;
                    int kp = il * 10 + q;
                    int ai = (((amt * 5 + (kp >> 3)) * 32 + alnb + (kp & 3)) << 2)
                             + ribase + (((kp >> 2) & 1) << 1);
                    uint32_t hi, lo;
                    split_pair(p0, p1, hi, lo);
                    sa[ai] = hi;
                    sa[5120 + ai] = lo;
                }
            }
        }
        {
            const uint4* bsrc = (const uint4*)(Wk2S + c * 10240);
            #pragma unroll
            for (int i = 0; i < 10; i++)
                ((uint4*)sb)[t + (i << 8)] = bsrc[t + (i << 8)];
        }
        __syncthreads();
        #pragma unroll
        for (int ks = 0; ks < 5; ks++) {
            uint4 ah0 = ((const uint4*)sa)[((wm * 2 + 0) * 5 + ks) * 32 + lane];
            uint4 al0 = ((const uint4*)sa)[1280 + ((wm * 2 + 0) * 5 + ks) * 32 + lane];
            uint4 ah1 = ((const uint4*)sa)[((wm * 2 + 1) * 5 + ks) * 32 + lane];
            uint4 al1 = ((const uint4*)sa)[1280 + ((wm * 2 + 1) * 5 + ks) * 32 + lane];
            #pragma unroll
            for (int j = 0; j < 8; j++) {
                int nt = wn * 8 + j;
                uint2 bh = ((const uint2*)sb)[(nt * 5 + ks) * 32 + lane];
                uint2 bl = ((const uint2*)sb)[2560 + (nt * 5 + ks) * 32 + lane];
                MMA_BF16(acc[0][j], ah0, bh);
                MMA_BF16(acc[0][j], ah0, bl);
                MMA_BF16(acc[0][j], al0, bh);
                MMA_BF16(acc[1][j], ah1, bh);
                MMA_BF16(acc[1][j], ah1, bl);
                MMA_BF16(acc[1][j], al1, bh);
            }
        }
    }

    // ---- epilogue: bias + LN(128) + relu + coalesced store to g_kout ----
    #pragma unroll
    for (int r = 0; r < 2; r++)
        #pragma unroll
        for (int j = 0; j < 8; j++) {
            int gc = wn * 64 + j * 8 + ((lane & 3) << 1);
            float b0 = bk2[gc], b1 = bk2[gc + 1];
            acc[r][j][0] += b0; acc[r][j][1] += b1;
            acc[r][j][2] += b0; acc[r][j][3] += b1;
        }
    float sum[2][2], sq[2][2];
    #pragma unroll
    for (int r = 0; r < 2; r++) {
        float s_lo=0.f, q_lo=0.f, s_hi=0.f, q_hi=0.f;
        #pragma unroll
        for (int j = 0; j < 8; j++) {
            s_lo += acc[r][j][0] + acc[r][j][1];
            q_lo += acc[r][j][0]*acc[r][j][0] + acc[r][j][1]*acc[r][j][1];
            s_hi += acc[r][j][2] + acc[r][j][3];
            q_hi += acc[r][j][2]*acc[r][j][2] + acc[r][j][3]*acc[r][j][3];
        }
        #pragma unroll
        for (int m = 1; m <= 2; m <<= 1) {
            s_lo += __shfl_xor_sync(0xffffffffu, s_lo, m);
            q_lo += __shfl_xor_sync(0xffffffffu, q_lo, m);
            s_hi += __shfl_xor_sync(0xffffffffu, s_hi, m);
            q_hi += __shfl_xor_sync(0xffffffffu, q_hi, m);
        }
        sum[r][0] = s_lo; sq[r][0] = q_lo;
        sum[r][1] = s_hi; sq[r][1] = q_hi;
        if ((lane & 3) == 0) {
            int rloc = wm * 32 + r * 16 + (lane >> 2);
            red[wn][rloc][0] = s_lo;     red[wn][rloc][1] = q_lo;
            red[wn][rloc + 8][0] = s_hi; red[wn][rloc + 8][1] = q_hi;
        }
    }
    __syncthreads();
    #pragma unroll
    for (int r = 0; r < 2; r++) {
        #pragma unroll
        for (int h = 0; h < 2; h++) {
            int rloc = wm * 32 + r * 16 + h * 8 + (lane >> 2);
            float ts = sum[r][h] + red[wn ^ 1][rloc][0];
            float tq = sq[r][h] + red[wn ^ 1][rloc][1];
            float mu = ts * (1.f / 128.f);
            float rs = rsqrtf(tq * (1.f / 128.f) - mu * mu + EPS);
            int gp = e0 + rloc;                // sorted position
            if (gp < E) {
                float* p = &g_kout[(size_t)gp * OUTD];
                #pragma unroll
                for (int j = 0; j < 8; j++) {
                    int gc = wn * 64 + j * 8 + ((lane & 3) << 1);
                    float g0 = lng[gc], g1 = lng[gc + 1];
                    float bb0 = lnb[gc], bb1 = lnb[gc + 1];
                    float o0 = fmaxf((acc[r][j][2*h  ]-mu)*rs*g0 + bb0, 0.f);
                    float o1 = fmaxf((acc[r][j][2*h+1]-mu)*rs*g1 + bb1, 0.f);
                    *(float2*)&p[gc] = make_float2(o0, o1);
                }
            }
        }
    }
}

// ---------------- GRU gates + relu + LN ----------------
__global__ void gates_kernel(const float* __restrict__ x,
                             const float* __restrict__ lng,
                             const float* __restrict__ lnb, int V) {
    int v = blockIdx.x * 4 + (threadIdx.x >> 5);
    if (v >= V) return;
    int lane = threadIdx.x & 31;
    const float* gi = &g_gi[(size_t)v * 384];
    const float* gh = &g_gh[(size_t)v * 384];
    float4 gir = *(const float4*)&gi[(lane << 2)];
    float4 giz = *(const float4*)&gi[128 + (lane << 2)];
    float4 gin = *(const float4*)&gi[256 + (lane << 2)];
    float4 ghr = *(const float4*)&gh[(lane << 2)];
    float4 ghz = *(const float4*)&gh[128 + (lane << 2)];
    float4 ghn = *(const float4*)&gh[256 + (lane << 2)];
    float4 xv  = *(const float4*)&x[(size_t)v * D + (lane << 2)];
    float h[4];
    #pragma unroll
    for (int i = 0; i < 4; i++) {
        float a_r = (&gir.x)[i] + (&ghr.x)[i];
        float a_z = (&giz.x)[i] + (&ghz.x)[i];
        float r = 1.f / (1.f + expf(-a_r));
        float z = 1.f / (1.f + expf(-a_z));
        float n = tanhf((&gin.x)[i] + r * (&ghn.x)[i]);
        float hh = (1.f - z) * n + z * (&xv.x)[i];
        h[i] = fmaxf(hh, 0.f);
    }
    float s = h[0] + h[1] + h[2] + h[3];
    #pragma unroll
    for (int m = 16; m; m >>= 1) s += __shfl_xor_sync(0xffffffffu, s, m);
    float mu = s * (1.f / 128.f);
    float q = 0.f;
    #pragma unroll
    for (int i = 0; i < 4; i++) { float d0 = h[i] - mu; q = fmaf(d0, d0, q); }
    #pragma unroll
    for (int m = 16; m; m >>= 1) q += __shfl_xor_sync(0xffffffffu, q, m);
    float rstd = rsqrtf(q * (1.f / 128.f) + EPS);
    float4 gv = *(const float4*)&lng[lane << 2];
    float4 b2 = *(const float4*)&lnb[lane << 2];
    float4 o;
    o.x = (h[0] - mu) * rstd * gv.x + b2.x;
    o.y = (h[1] - mu) * rstd * gv.y + b2.y;
    o.z = (h[2] - mu) * rstd * gv.z + b2.z;
    o.w = (h[3] - mu) * rstd * gv.w + b2.w;
    *(float4*)&g_gru[(size_t)v * D + (lane << 2)] = o;
}

// ---------------- host ----------------
extern "C" void kernel_launch(void* const* d_in, const int* in_sizes, int n_in,
                              void* d_out, int out_size) {
    const float* node   = (const float*)d_in[0];
    const int*   src    = (const int*)  d_in[1];
    const int*   dst    = (const int*)  d_in[2];
    const float* W_edge = (const float*)d_in[3];
    const float* b_edge = (const float*)d_in[4];
    const float* W_pn   = (const float*)d_in[5];
    const float* b_pn   = (const float*)d_in[6];
    const float* W_ih   = (const float*)d_in[7];
    const float* b_ih   = (const float*)d_in[8];
    const float* W_hh   = (const float*)d_in[9];
    const float* b_hh   = (const float*)d_in[10];
    const float* ln_g   = (const float*)d_in[11];
    const float* ln_b   = (const float*)d_in[12];
    const float* Wk1    = (const float*)d_in[13];
    const float* bk1    = (const float*)d_in[14];
    const float* lnk1_g = (const float*)d_in[15];
    const float* lnk1_b = (const float*)d_in[16];
    const float* Wk2    = (const float*)d_in[17];
    const float* bk2    = (const float*)d_in[18];
    const float* lnk2_g = (const float*)d_in[19];
    const float* lnk2_b = (const float*)d_in[20];
    const float* Wc     = (const float*)d_in[21];
    const float* bc     = (const float*)d_in[22];
    const float* lnc_g  = (const float*)d_in[23];
    const float* lnc_b  = (const float*)d_in[24];
    int V = in_sizes[0] / D;
    int E = in_sizes[1];
    float* out = (float*)d_out;

    float *p_asum, *p_lmax, *p_hv, *p_ctx, *p_kf, *p_gi, *p_gh, *p_gru;
    int *p_cnt, *p_cnt2;
    uint32_t *p_WpnS, *p_WihS, *p_WhhS, *p_WcS, *p_Wk2S;
    uint32_t *p_Anode, *p_Actx, *p_Acat;
    cudaGetSymbolAddress((void**)&p_asum,  g_asum);
    cudaGetSymbolAddress((void**)&p_lmax,  g_lmax);
    cudaGetSymbolAddress((void**)&p_hv,    g_hv);
    cudaGetSymbolAddress((void**)&p_ctx,   g_ctx);
    cudaGetSymbolAddress((void**)&p_kf,    g_kf);
    cudaGetSymbolAddress((void**)&p_gi,    g_gi);
    cudaGetSymbolAddress((void**)&p_gh,    g_gh);
    cudaGetSymbolAddress((void**)&p_gru,   g_gru);
    cudaGetSymbolAddress((void**)&p_cnt,   g_cnt);
    cudaGetSymbolAddress((void**)&p_cnt2,  g_cnt2);
    cudaGetSymbolAddress((void**)&p_WpnS,  g_WpnS);
    cudaGetSymbolAddress((void**)&p_WihS,  g_WihS);
    cudaGetSymbolAddress((void**)&p_WhhS,  g_WhhS);
    cudaGetSymbolAddress((void**)&p_WcS,   g_WcS);
    cudaGetSymbolAddress((void**)&p_Wk2S,  g_Wk2S);
    cudaGetSymbolAddress((void**)&p_Anode, g_Anode);
    cudaGetSymbolAddress((void**)&p_Actx,  g_Actx);
    cudaGetSymbolAddress((void**)&p_Acat,  g_Acat);

    static bool attr_set = false;
    if (!attr_set) {
        cudaFuncSetAttribute(kron_mma2, cudaFuncAttributeMaxDynamicSharedMemorySize, 103000);
        attr_set = true;
    }

    int NBv = (V + 63) / 64;

    // zero small accumulators + sort counters
    {
        int n4 = V / 4;
        zero_kernel<<<(n4 + 255) / 256, 256>>>((float4*)p_asum, n4);
        zero_kernel<<<(n4 + 255) / 256, 256>>>((float4*)p_lmax, n4);
        zeroi_kernel<<<(V + 255) / 256, 256>>>(p_cnt, V);
        zeroi_kernel<<<(V + 255) / 256, 256>>>(p_cnt2, V);
    }

    // CSR build
    hist_kernel<<<(E + 255) / 256, 256>>>(dst, E);
    scan_kernel<<<1, 1024>>>(V, E);
    scatter_kernel<<<(E + 255) / 256, 256>>>(dst, E);

    // pack weights
    pack_w_frag<<<(64 * 128 + 255) / 256, 256>>>(W_pn, 128, 128, 0, p_WpnS);
    pack_w_frag<<<(64 * 384 + 255) / 256, 256>>>(W_ih, 128, 384, 1, p_WihS);
    pack_w_frag<<<(64 * 384 + 255) / 256, 256>>>(W_hh, 128, 384, 1, p_WhhS);
    pack_w_frag<<<(128 * 128 + 255) / 256, 256>>>(Wc, 256, 128, 0, p_WcS);
    pack_wk2<<<(200 * 128 + 255) / 256, 256>>>(Wk2, p_Wk2S);

    // pack node activations
    pack_act<<<NBv, 256>>>(node, 128, nullptr, 0, 0, p_Anode, V);

    npj_kernel<<<(V + 3) / 4, 128>>>(node, Wk1, bk1, lnk1_g, lnk1_b, V);
    logits_kernel<<<(E + 3) / 4, 128>>>(node, src, dst, W_edge, b_edge, E);
    expsum_kernel<<<(E + 255) / 256, 256>>>(dst, E);

    // hv = node @ W_pn + b_pn
    mma_gemm<<<dim3(NBv, 1), 256>>>(p_Anode, p_WpnS, 4, 128,
                                    b_pn, nullptr, nullptr, p_hv, V);

    // edge kron GEMM (sorted order) -> g_kout rows
    kron_mma2<<<(E + 127) / 128, 256, 102400>>>(src, dst, p_Wk2S,
                                                bk2, lnk2_g, lnk2_b, E);

    // kf[v] = sum of its sorted kout rows (sequential reads)
    kf_csr<<<(V + 7) / 8, 256>>>(V);

    // ctx[v] = relu(sum hv[src]*a/asum) via CSR (no atomics)
    ctx_csr<<<(V + 7) / 8, 256>>>(src, V);

    // pack ctx (relu already applied)
    pack_act<<<NBv, 256>>>(p_ctx, 128, nullptr, 0, 0, p_Actx, V);

    // gi / gh GEMMs
    mma_gemm<<<dim3(NBv, 3), 256>>>(p_Actx, p_WihS, 4, 384,
                                    b_ih, nullptr, nullptr, p_gi, V);
    mma_gemm<<<dim3(NBv, 3), 256>>>(p_Anode, p_WhhS, 4, 384,
                                    b_hh, nullptr, nullptr, p_gh, V);

    gates_kernel<<<(V + 3) / 4, 128>>>(node, ln_g, ln_b, V);

    // pack cat(gru, kf)
    pack_act<<<NBv, 256>>>(p_gru, 128, p_kf, 128, 0, p_Acat, V);

    // out = relu(LN(cat @ Wc + bc))
    mma_gemm<<<dim3(NBv, 1), 256>>>(p_Acat, p_WcS, 8, 128,
                                    bc, lnc_g, lnc_b, out, V);
}

// round 7
// speedup vs baseline: 1.1763x; 1.1751x over previous
#include <cuda_runtime.h>
#include <cuda_bf16.h>
#include <math.h>
#include <stdint.h>

#define D     128
#define KP    20
#define VMAX  100000
#define EMAX  400000
#define EPS   1e-5f
#define NBMAX 1563   // (VMAX+63)/64

// ---------------- scratch (device globals; no allocations) ----------------
__device__ float g_npj  [VMAX * KP];
__device__ float g_logit[EMAX];
__device__ float g_aexp [EMAX];
__device__ float g_lmax [VMAX];
__device__ float g_asum [VMAX];
__device__ float g_hv   [VMAX * D];
__device__ float g_ctx  [VMAX * D];
__device__ float g_kf   [VMAX * D];
__device__ float g_gi   [VMAX * 3 * D];
__device__ float g_gh   [VMAX * 3 * D];
__device__ float g_gru  [VMAX * D];

// fragment-ordered bf16 hi/lo WEIGHT streams (per (ny,chunk): 4096 u32)
__device__ uint32_t g_WpnS[1 * 4 * 4096];
__device__ uint32_t g_WihS[3 * 4 * 4096];
__device__ uint32_t g_WhhS[3 * 4 * 4096];
__device__ uint32_t g_WcS [1 * 8 * 4096];
__device__ uint32_t g_Wk2S[5 * 10240];

// COMPACT fragment-ordered bf16 hi/lo ACTIVATION streams
// per (mblock64, chunk32): 2048 u32 = hi[0,1024) lo[1024,2048)
__device__ uint32_t g_Anode[(size_t)NBMAX * 4 * 2048];
__device__ uint32_t g_Actx [(size_t)NBMAX * 4 * 2048];
__device__ uint32_t g_Acat [(size_t)NBMAX * 8 * 2048];

// ---------------- fast bf16 hi/lo split (truncation) ----------------
__device__ __forceinline__ void split_pair(float a0, float a1,
                                           uint32_t& hi, uint32_t& lo) {
    uint32_t b0 = __float_as_uint(a0), b1 = __float_as_uint(a1);
    uint32_t hp;
    asm("prmt.b32 %0, %1, %2, 0x7632;" : "=r"(hp) : "r"(b0), "r"(b1));
    float l0 = a0 - __uint_as_float(b0 & 0xffff0000u);
    float l1 = a1 - __uint_as_float(b1 & 0xffff0000u);
    __nv_bfloat162 lp = __floats2bfloat162_rn(l0, l1);
    hi = hp; lo = *(uint32_t*)&lp;
}

#define MMA_BF16(c, A, B) asm volatile( \
    "mma.sync.aligned.m16n8k16.row.col.f32.bf16.bf16.f32 " \
    "{%0,%1,%2,%3}, {%4,%5,%6,%7}, {%8,%9}, {%0,%1,%2,%3};\n" \
    : "+f"(c[0]), "+f"(c[1]), "+f"(c[2]), "+f"(c[3]) \
    : "r"(A.x), "r"(A.y), "r"(A.z), "r"(A.w), "r"(B.x), "r"(B.y))

// ---------------- utility kernels ----------------
__global__ void zero_kernel(float4* p, int n4) {
    int i = blockIdx.x * blockDim.x + threadIdx.x;
    if (i < n4) p[i] = make_float4(0.f, 0.f, 0.f, 0.f);
}

// pack weights into fragment stream: per (ny, chunk): hi[0,2048) lo[2048,4096)
__global__ void pack_w_frag(const float* __restrict__ W, int K, int Ntot,
                            int transp, uint32_t* __restrict__ out) {
    int idx = blockIdx.x * blockDim.x + threadIdx.x;
    int total = (K / 2) * Ntot;
    if (idx >= total) return;
    int kp = idx / Ntot, n = idx - kp * Ntot;
    int k0 = 2 * kp;
    float w0, w1;
    if (transp) { w0 = W[n * K + k0]; w1 = W[n * K + k0 + 1]; }
    else        { w0 = W[k0 * Ntot + n]; w1 = W[(k0 + 1) * Ntot + n]; }
    int c = kp >> 4, kpl = kp & 15;
    int ny = n >> 7, nl = n & 127;
    int bi = ((((nl >> 3) * 2 + (kpl >> 3)) * 32 + ((nl & 7) << 2) + (kpl & 3)) << 1)
             + ((kpl >> 2) & 1);
    size_t base = ((size_t)(ny * (K >> 5) + c)) << 12;
    uint32_t hi, lo;
    split_pair(w0, w1, hi, lo);
    out[base + bi] = hi;
    out[base + 2048 + bi] = lo;
}

// Wk2 [400][128] -> kron stream: per chunk(5): hi[0,5120) lo[5120,10240)
__global__ void pack_wk2(const float* __restrict__ W, uint32_t* __restrict__ out) {
    int idx = blockIdx.x * blockDim.x + threadIdx.x;
    if (idx >= 200 * 128) return;
    int kp = idx >> 7, n = idx & 127;
    float w0 = W[(2 * kp) * 128 + n];
    float w1 = W[(2 * kp + 1) * 128 + n];
    int c = kp / 40, kpl = kp - c * 40;
    int bi = ((((n >> 3) * 5 + (kpl >> 3)) * 32 + ((n & 7) << 2) + (kpl & 3)) << 1)
             + ((kpl >> 2) & 1);
    uint32_t hi, lo;
    split_pair(w0, w1, hi, lo);
    out[c * 10240 + bi] = hi;
    out[c * 10240 + 5120 + bi] = lo;
}

// COMPACT activation pack: per (mb, c): 1024 pairs hi + 1024 lo.
// idx = mt*256 + ks*128 + lane*4 + ri  (matches mma A-fragment reader)
__global__ void pack_act(const float* __restrict__ X0, int K0,
                         const float* __restrict__ X1, int K1, int relu,
                         uint32_t* __restrict__ out, int V) {
    int t = threadIdx.x;
    int mb = blockIdx.x;
    int K = K0 + K1;
    int Kch = K >> 5;
    for (int it = 0; it < Kch * 4; it++) {
        int c = it >> 2;
        int idx = ((it & 3) << 8) + t;       // 0..1023 within chunk
        int mt = idx >> 8;
        int ks = (idx >> 7) & 1;
        int ln = (idx >> 2) & 31;
        int ri = idx & 3;
        int row = mb * 64 + mt * 16 + (ri & 1) * 8 + (ln >> 2);
        if (row >= V) row = V - 1;
        int k = c * 32 + ks * 16 + ((ri >> 1) << 3) + ((ln & 3) << 1);
        float2 a;
        if (k < K0) a = *(const float2*)&X0[(size_t)row * K0 + k];
        else        a = *(const float2*)&X1[(size_t)row * K1 + (k - K0)];
        if (relu) { a.x = fmaxf(a.x, 0.f); a.y = fmaxf(a.y, 0.f); }
        uint32_t hi, lo;
        split_pair(a.x, a.y, hi, lo);
        size_t base = ((size_t)(mb * Kch + c)) << 11;
        out[base + idx] = hi;
        out[base + 1024 + idx] = lo;
    }
}

// ---------------- npj = relu(LN(x @ Wk1 + bk1)), [V,20] ----------------
__global__ void npj_kernel(const float* __restrict__ x,
                           const float* __restrict__ Wk1,
                           const float* __restrict__ bk1,
                           const float* __restrict__ g,
                           const float* __restrict__ b, int V) {
    __shared__ float xs[4][D];
    int warp = threadIdx.x >> 5, lane = threadIdx.x & 31;
    int v  = blockIdx.x * 4 + warp;
    int vc = v < V ? v : V - 1;
    *(float4*)&xs[warp][lane << 2] = *(const float4*)&x[vc * D + (lane << 2)];
    __syncwarp();
    float y = 0.f;
    if (lane < KP) {
        #pragma unroll 8
        for (int k = 0; k < D; k++) y = fmaf(xs[warp][k], Wk1[k * KP + lane], y);
        y += bk1[lane];
    }
    float s = (lane < KP) ? y : 0.f;
    #pragma unroll
    for (int m = 16; m; m >>= 1) s += __shfl_xor_sync(0xffffffffu, s, m);
    float mu = s * (1.f / KP);
    float dv = (lane < KP) ? (y - mu) * (y - mu) : 0.f;
    #pragma unroll
    for (int m = 16; m; m >>= 1) dv += __shfl_xor_sync(0xffffffffu, dv, m);
    float rstd = rsqrtf(dv * (1.f / KP) + EPS);
    if (v < V && lane < KP) {
        float val = (y - mu) * rstd * g[lane] + b[lane];
        g_npj[v * KP + lane] = fmaxf(val, 0.f);
    }
}

// ---------------- edge logits + segment max ----------------
__global__ void logits_kernel(const float* __restrict__ x,
                              const int* __restrict__ src,
                              const int* __restrict__ dst,
                              const float* __restrict__ We,
                              const float* __restrict__ be, int E) {
    int e = blockIdx.x * 4 + (threadIdx.x >> 5);
    if (e >= E) return;
    int lane = threadIdx.x & 31;
    int sn = src[e], dn = dst[e];
    float4 xd = *(const float4*)&x[dn * D + (lane << 2)];
    float4 w1 = *(const float4*)&We[lane << 2];
    float4 xv = *(const float4*)&x[sn * D + (lane << 2)];
    float4 w2 = *(const float4*)&We[D + (lane << 2)];
    float p = xd.x * w1.x + xd.y * w1.y + xd.z * w1.z + xd.w * w1.w
            + xv.x * w2.x + xv.y * w2.y + xv.z * w2.z + xv.w * w2.w;
    #pragma unroll
    for (int m = 16; m; m >>= 1) p += __shfl_xor_sync(0xffffffffu, p, m);
    if (lane == 0) {
        float lg = fmaxf(p + be[0], 0.f);
        g_logit[e] = lg;
        atomicMax((int*)&g_lmax[dn], __float_as_int(lg));  // valid: lg >= 0
    }
}

// ---------------- a = exp(logit - lmax[dst]); asum += a ----------------
__global__ void expsum_kernel(const int* __restrict__ dst, int E) {
    int e = blockIdx.x * blockDim.x + threadIdx.x;
    if (e >= E) return;
    int dn = dst[e];
    float a = expf(g_logit[e] - g_lmax[dn]);
    g_aexp[e] = a;
    atomicAdd(&g_asum[dn], a);
}

// ---------------- context scatter (vector atomics) ----------------
__global__ void context_kernel(const int* __restrict__ src,
                               const int* __restrict__ dst, int E) {
    int e = blockIdx.x * 8 + (threadIdx.x >> 5);
    if (e >= E) return;
    int lane = threadIdx.x & 31;
    int sn = src[e], dn = dst[e];
    float coef = g_aexp[e] / g_asum[dn];
    float4 h = *(const float4*)&g_hv[(size_t)sn * D + (lane << 2)];
    atomicAdd((float4*)&g_ctx[(size_t)dn * D + (lane << 2)],
              make_float4(h.x * coef, h.y * coef, h.z * coef, h.w * coef));
}

// =====================================================================
// Node GEMM via mma.bf16 3-pass, compact A stream, reg-prefetch dbl-buffer.
// Tile M=64 x N=128 (grid.y over N tiles). 8 warps: wm=w&3, wn=w>>2.
// =====================================================================
__global__ __launch_bounds__(256)
void mma_gemm(const uint32_t* __restrict__ As, const uint32_t* __restrict__ Bs,
              int Kchunks, int Ntot,
              const float* __restrict__ bias,
              const float* __restrict__ lng, const float* __restrict__ lnb,
              float* __restrict__ out, int V) {
    __shared__ uint32_t sa[2048];   // hi [0,1024) lo [1024,2048)
    __shared__ uint32_t sb[4096];   // hi [0,2048) lo [2048,4096)
    __shared__ float red[2][64][2];

    int t = threadIdx.x;
    int lane = t & 31, w = t >> 5;
    int wm = w & 3, wn = w >> 2;
    int row0 = blockIdx.x * 64;
    int nb = blockIdx.y * 128;

    float acc[8][4];
    #pragma unroll
    for (int j = 0; j < 8; j++) { acc[j][0]=acc[j][1]=acc[j][2]=acc[j][3]=0.f; }

    const uint4* ag = (const uint4*)(As + (size_t)blockIdx.x * Kchunks * 2048);
    const uint4* bg = (const uint4*)(Bs + (size_t)blockIdx.y * Kchunks * 4096);

    uint4 pa0, pa1, pb0, pb1, pb2, pb3;
    pa0 = ag[t]; pa1 = ag[t + 256];
    pb0 = bg[t]; pb1 = bg[t + 256]; pb2 = bg[t + 512]; pb3 = bg[t + 768];

    for (int c = 0; c < Kchunks; c++) {
        __syncthreads();
        ((uint4*)sa)[t]       = pa0; ((uint4*)sa)[t + 256] = pa1;
        ((uint4*)sb)[t]       = pb0; ((uint4*)sb)[t + 256] = pb1;
        ((uint4*)sb)[t + 512] = pb2; ((uint4*)sb)[t + 768] = pb3;
        __syncthreads();
        if (c + 1 < Kchunks) {
            const uint4* a4 = ag + (size_t)(c + 1) * 512;
            const uint4* b4 = bg + (size_t)(c + 1) * 1024;
            pa0 = a4[t]; pa1 = a4[t + 256];
            pb0 = b4[t]; pb1 = b4[t + 256]; pb2 = b4[t + 512]; pb3 = b4[t + 768];
        }
        #pragma unroll
        for (int ks = 0; ks < 2; ks++) {
            uint4 ah = ((const uint4*)sa)[(wm * 2 + ks) * 32 + lane];
            uint4 al = *(const uint4*)&sa[1024 + (((wm * 2 + ks) * 32 + lane) << 2)];
            #pragma unroll
            for (int j = 0; j < 8; j++) {
                int nt = wn * 8 + j;
                uint2 bh = ((const uint2*)sb)[(nt * 2 + ks) * 32 + lane];
                uint2 bl = *(const uint2*)&sb[2048 + (((nt * 2 + ks) * 32 + lane) << 1)];
                MMA_BF16(acc[j], ah, bh);
                MMA_BF16(acc[j], ah, bl);
                MMA_BF16(acc[j], al, bh);
            }
        }
    }

    int rl = row0 + wm * 16 + (lane >> 2);
    int rh = rl + 8;
    #pragma unroll
    for (int j = 0; j < 8; j++) {
        int gc = nb + wn * 64 + j * 8 + ((lane & 3) << 1);
        float b0 = bias[gc], b1 = bias[gc + 1];
        acc[j][0] += b0; acc[j][1] += b1; acc[j][2] += b0; acc[j][3] += b1;
    }
    if (lng == nullptr) {
        #pragma unroll
        for (int j = 0; j < 8; j++) {
            int gc = nb + wn * 64 + j * 8 + ((lane & 3) << 1);
            if (rl < V) *(float2*)&out[(size_t)rl * Ntot + gc] = make_float2(acc[j][0], acc[j][1]);
            if (rh < V) *(float2*)&out[(size_t)rh * Ntot + gc] = make_float2(acc[j][2], acc[j][3]);
        }
    } else {
        float s_lo=0.f, q_lo=0.f, s_hi=0.f, q_hi=0.f;
        #pragma unroll
        for (int j = 0; j < 8; j++) {
            s_lo += acc[j][0] + acc[j][1];
            q_lo += acc[j][0]*acc[j][0] + acc[j][1]*acc[j][1];
            s_hi += acc[j][2] + acc[j][3];
            q_hi += acc[j][2]*acc[j][2] + acc[j][3]*acc[j][3];
        }
        #pragma unroll
        for (int m = 1; m <= 2; m <<= 1) {
            s_lo += __shfl_xor_sync(0xffffffffu, s_lo, m);
            q_lo += __shfl_xor_sync(0xffffffffu, q_lo, m);
            s_hi += __shfl_xor_sync(0xffffffffu, s_hi, m);
            q_hi += __shfl_xor_sync(0xffffffffu, q_hi, m);
        }
        int rloc = wm * 16 + (lane >> 2);
        if ((lane & 3) == 0) {
            red[wn][rloc][0] = s_lo;   red[wn][rloc][1] = q_lo;
            red[wn][rloc+8][0] = s_hi; red[wn][rloc+8][1] = q_hi;
        }
        __syncthreads();
        float ts_lo = s_lo + red[wn ^ 1][rloc][0];
        float tq_lo = q_lo + red[wn ^ 1][rloc][1];
        float ts_hi = s_hi + red[wn ^ 1][rloc + 8][0];
        float tq_hi = q_hi + red[wn ^ 1][rloc + 8][1];
        float mu_lo = ts_lo * (1.f/128.f);
        float mu_hi = ts_hi * (1.f/128.f);
        float rs_lo = rsqrtf(tq_lo * (1.f/128.f) - mu_lo*mu_lo + EPS);
        float rs_hi = rsqrtf(tq_hi * (1.f/128.f) - mu_hi*mu_hi + EPS);
        #pragma unroll
        for (int j = 0; j < 8; j++) {
            int gc = wn * 64 + j * 8 + ((lane & 3) << 1);
            float g0 = lng[gc], g1 = lng[gc+1];
            float bb0 = lnb[gc], bb1 = lnb[gc+1];
            if (rl < V) {
                float o0 = fmaxf((acc[j][0]-mu_lo)*rs_lo*g0 + bb0, 0.f);
                float o1 = fmaxf((acc[j][1]-mu_lo)*rs_lo*g1 + bb1, 0.f);
                *(float2*)&out[(size_t)rl * 128 + gc] = make_float2(o0, o1);
            }
            if (rh < V) {
                float o2 = fmaxf((acc[j][2]-mu_hi)*rs_hi*g0 + bb0, 0.f);
                float o3 = fmaxf((acc[j][3]-mu_hi)*rs_hi*g1 + bb1, 0.f);
                *(float2*)&out[(size_t)rh * 128 + gc] = make_float2(o2, o3);
            }
        }
    }
}

// =====================================================================
// Kron edge GEMM (R3 version): 128 edges x 128 outs, K=400 (5 chunks of 80),
// LN + relu + atomic scatter to g_kf[dst].
// =====================================================================
__global__ __launch_bounds__(256, 2)
void kron_mma(const int* __restrict__ src, const int* __restrict__ dst,
              const uint32_t* __restrict__ Wk2S,
              const float* __restrict__ bk2,
              const float* __restrict__ lng, const float* __restrict__ lnb,
              int E) {
    extern __shared__ uint32_t dsm[];
    uint32_t* sa = dsm;               // 10240: hi [0,5120) lo [5120,10240)
    uint32_t* sb = dsm + 10240;       // 10240
    float* Ss = (float*)(dsm + 20480);   // 128*20
    float* Ds = Ss + 2560;               // 128*20
    __shared__ int ssrc[128], sdst[128];
    __shared__ float red[2][128][2];

    int t = threadIdx.x;
    int lane = t & 31, w = t >> 5;
    int wm = w & 3, wn = w >> 2;
    int e0 = blockIdx.x * 128;

    if (t < 128) {
        int ee = e0 + t; if (ee >= E) ee = E - 1;
        ssrc[t] = src[ee];
        sdst[t] = dst[ee];
    }
    __syncthreads();
    for (int idx = t; idx < 640; idx += 256) {
        int e = idx / 5, q = idx - e * 5;
        ((float4*)Ss)[idx] = *(const float4*)&g_npj[ssrc[e] * KP + q * 4];
        ((float4*)Ds)[idx] = *(const float4*)&g_npj[sdst[e] * KP + q * 4];
    }

    float acc[2][8][4];
    #pragma unroll
    for (int r = 0; r < 2; r++)
        #pragma unroll
        for (int j = 0; j < 8; j++) { acc[r][j][0]=acc[r][j][1]=acc[r][j][2]=acc[r][j][3]=0.f; }

    int be = t >> 1, ih = t & 1;
    int amt = be >> 4;
    int ribase = (be >> 3) & 1;
    int alnb = (be & 7) << 2;

    for (int c = 0; c < 5; c++) {
        __syncthreads();
        {
            const float* ds = &Ds[be * 20];
            #pragma unroll
            for (int iv = 0; iv < 2; iv++) {
                int il = ih * 2 + iv;
                float sv = Ss[be * 20 + c * 4 + il];
                #pragma unroll
                for (int q = 0; q < 10; q++) {
                    float2 d = *(const float2*)&ds[2 * q];
                    float p0 = sv * d.x, p1 = sv * d.y;
                    int kp = il * 10 + q;
                    int ai = (((amt * 5 + (kp >> 3)) * 32 + alnb + (kp & 3)) << 2)
                             + ribase + (((kp >> 2) & 1) << 1);
                    uint32_t hi, lo;
                    split_pair(p0, p1, hi, lo);
                    sa[ai] = hi;
                    sa[5120 + ai] = lo;
                }
            }
        }
        {
            const uint4* bsrc = (const uint4*)(Wk2S + c * 10240);
            #pragma unroll
            for (int i = 0; i < 10; i++)
                ((uint4*)sb)[t + (i << 8)] = bsrc[t + (i << 8)];
        }
        __syncthreads();
        #pragma unroll
        for (int ks = 0; ks < 5; ks++) {
            uint4 ah0 = ((const uint4*)sa)[((wm * 2 + 0) * 5 + ks) * 32 + lane];
            uint4 al0 = ((const uint4*)sa)[1280 + ((wm * 2 + 0) * 5 + ks) * 32 + lane];
            uint4 ah1 = ((const uint4*)sa)[((wm * 2 + 1) * 5 + ks) * 32 + lane];
            uint4 al1 = ((const uint4*)sa)[1280 + ((wm * 2 + 1) * 5 + ks) * 32 + lane];
            #pragma unroll
            for (int j = 0; j < 8; j++) {
                int nt = wn * 8 + j;
                uint2 bh = ((const uint2*)sb)[(nt * 5 + ks) * 32 + lane];
                uint2 bl = ((const uint2*)sb)[2560 + (nt * 5 + ks) * 32 + lane];
                MMA_BF16(acc[0][j], ah0, bh);
                MMA_BF16(acc[0][j], ah0, bl);
                MMA_BF16(acc[0][j], al0, bh);
                MMA_BF16(acc[1][j], ah1, bh);
                MMA_BF16(acc[1][j], ah1, bl);
                MMA_BF16(acc[1][j], al1, bh);
            }
        }
    }

    #pragma unroll
    for (int r = 0; r < 2; r++)
        #pragma unroll
        for (int j = 0; j < 8; j++) {
            int gc = wn * 64 + j * 8 + ((lane & 3) << 1);
            float b0 = bk2[gc], b1 = bk2[gc + 1];
            acc[r][j][0] += b0; acc[r][j][1] += b1;
            acc[r][j][2] += b0; acc[r][j][3] += b1;
        }
    float sum[2][2], sq[2][2];
    #pragma unroll
    for (int r = 0; r < 2; r++) {
        float s_lo=0.f, q_lo=0.f, s_hi=0.f, q_hi=0.f;
        #pragma unroll
        for (int j = 0; j < 8; j++) {
            s_lo += acc[r][j][0] + acc[r][j][1];
            q_lo += acc[r][j][0]*acc[r][j][0] + acc[r][j][1]*acc[r][j][1];
            s_hi += acc[r][j][2] + acc[r][j][3];
            q_hi += acc[r][j][2]*acc[r][j][2] + acc[r][j][3]*acc[r][j][3];
        }
        #pragma unroll
        for (int m = 1; m <= 2; m <<= 1) {
            s_lo += __shfl_xor_sync(0xffffffffu, s_lo, m);
            q_lo += __shfl_xor_sync(0xffffffffu, q_lo, m);
            s_hi += __shfl_xor_sync(0xffffffffu, s_hi, m);
            q_hi += __shfl_xor_sync(0xffffffffu, q_hi, m);
        }
        sum[r][0] = s_lo; sq[r][0] = q_lo;
        sum[r][1] = s_hi; sq[r][1] = q_hi;
        if ((lane & 3) == 0) {
            int rloc = wm * 32 + r * 16 + (lane >> 2);
            red[wn][rloc][0] = s_lo;     red[wn][rloc][1] = q_lo;
            red[wn][rloc + 8][0] = s_hi; red[wn][rloc + 8][1] = q_hi;
        }
    }
    __syncthreads();
    #pragma unroll
    for (int r = 0; r < 2; r++) {
        #pragma unroll
        for (int h = 0; h < 2; h++) {
            int rloc = wm * 32 + r * 16 + h * 8 + (lane >> 2);
            float ts = sum[r][h] + red[wn ^ 1][rloc][0];
            float tq = sq[r][h] + red[wn ^ 1][rloc][1];
            float mu = ts * (1.f / 128.f);
            float rs = rsqrtf(tq * (1.f / 128.f) - mu * mu + EPS);
            int ge = e0 + rloc;
            if (ge < E) {
                int dn = sdst[rloc];
                #pragma unroll
                for (int j = 0; j < 8; j++) {
                    int gc = wn * 64 + j * 8 + ((lane & 3) << 1);
                    float g0 = lng[gc], g1 = lng[gc + 1];
                    float bb0 = lnb[gc], bb1 = lnb[gc + 1];
                    float* p = &g_kf[(size_t)dn * 128 + gc];
                    atomicAdd(p,     fmaxf((acc[r][j][2*h  ]-mu)*rs*g0 + bb0, 0.f));
                    atomicAdd(p + 1, fmaxf((acc[r][j][2*h+1]-mu)*rs*g1 + bb1, 0.f));
                }
            }
        }
    }
}

// ---------------- GRU gates + relu + LN ----------------
__global__ void gates_kernel(const float* __restrict__ x,
                             const float* __restrict__ lng,
                             const float* __restrict__ lnb, int V) {
    int v = blockIdx.x * 4 + (threadIdx.x >> 5);
    if (v >= V) return;
    int lane = threadIdx.x & 31;
    const float* gi = &g_gi[(size_t)v * 384];
    const float* gh = &g_gh[(size_t)v * 384];
    float4 gir = *(const float4*)&gi[(lane << 2)];
    float4 giz = *(const float4*)&gi[128 + (lane << 2)];
    float4 gin = *(const float4*)&gi[256 + (lane << 2)];
    float4 ghr = *(const float4*)&gh[(lane << 2)];
    float4 ghz = *(const float4*)&gh[128 + (lane << 2)];
    float4 ghn = *(const float4*)&gh[256 + (lane << 2)];
    float4 xv  = *(const float4*)&x[(size_t)v * D + (lane << 2)];
    float h[4];
    #pragma unroll
    for (int i = 0; i < 4; i++) {
        float r = 1.f / (1.f + expf(-((&gir.x)[i] + (&ghr.x)[i])));
        float z = 1.f / (1.f + expf(-((&giz.x)[i] + (&ghz.x)[i])));
        float n = tanhf((&gin.x)[i] + r * (&ghn.x)[i]);
        h[i] = fmaxf((1.f - z) * n + z * (&xv.x)[i], 0.f);
    }
    float s = h[0] + h[1] + h[2] + h[3];
    #pragma unroll
    for (int m = 16; m; m >>= 1) s += __shfl_xor_sync(0xffffffffu, s, m);
    float mu = s * (1.f / 128.f), q = 0.f;
    #pragma unroll
    for (int i = 0; i < 4; i++) { float d0 = h[i] - mu; q = fmaf(d0, d0, q); }
    #pragma unroll
    for (int m = 16; m; m >>= 1) q += __shfl_xor_sync(0xffffffffu, q, m);
    float rstd = rsqrtf(q * (1.f / 128.f) + EPS);
    float4 gv = *(const float4*)&lng[lane << 2];
    float4 b2 = *(const float4*)&lnb[lane << 2];
    float4 o;
    o.x = (h[0] - mu) * rstd * gv.x + b2.x;
    o.y = (h[1] - mu) * rstd * gv.y + b2.y;
    o.z = (h[2] - mu) * rstd * gv.z + b2.z;
    o.w = (h[3] - mu) * rstd * gv.w + b2.w;
    *(float4*)&g_gru[(size_t)v * D + (lane << 2)] = o;
}

// ---------------- host ----------------
extern "C" void kernel_launch(void* const* d_in, const int* in_sizes, int n_in,
                              void* d_out, int out_size) {
    const float* node   = (const float*)d_in[0];
    const int*   src    = (const int*)  d_in[1];
    const int*   dst    = (const int*)  d_in[2];
    const float* W_edge = (const float*)d_in[3];
    const float* b_edge = (const float*)d_in[4];
    const float* W_pn   = (const float*)d_in[5];
    const float* b_pn   = (const float*)d_in[6];
    const float* W_ih   = (const float*)d_in[7];
    const float* b_ih   = (const float*)d_in[8];
    const float* W_hh   = (const float*)d_in[9];
    const float* b_hh   = (const float*)d_in[10];
    const float* ln_g   = (const float*)d_in[11];
    const float* ln_b   = (const float*)d_in[12];
    const float* Wk1    = (const float*)d_in[13];
    const float* bk1    = (const float*)d_in[14];
    const float* lnk1_g = (const float*)d_in[15];
    const float* lnk1_b = (const float*)d_in[16];
    const float* Wk2    = (const float*)d_in[17];
    const float* bk2    = (const float*)d_in[18];
    const float* lnk2_g = (const float*)d_in[19];
    const float* lnk2_b = (const float*)d_in[20];
    const float* Wc     = (const float*)d_in[21];
    const float* bc     = (const float*)d_in[22];
    const float* lnc_g  = (const float*)d_in[23];
    const float* lnc_b  = (const float*)d_in[24];
    int V = in_sizes[0] / D;
    int E = in_sizes[1];
    float* out = (float*)d_out;

    float *p_asum, *p_lmax, *p_hv, *p_ctx, *p_kf, *p_gi, *p_gh, *p_gru;
    uint32_t *p_WpnS, *p_WihS, *p_WhhS, *p_WcS, *p_Wk2S;
    uint32_t *p_An, *p_Ac, *p_Aq;
    cudaGetSymbolAddress((void**)&p_asum, g_asum);
    cudaGetSymbolAddress((void**)&p_lmax, g_lmax);
    cudaGetSymbolAddress((void**)&p_hv,   g_hv);
    cudaGetSymbolAddress((void**)&p_ctx,  g_ctx);
    cudaGetSymbolAddress((void**)&p_kf,   g_kf);
    cudaGetSymbolAddress((void**)&p_gi,   g_gi);
    cudaGetSymbolAddress((void**)&p_gh,   g_gh);
    cudaGetSymbolAddress((void**)&p_gru,  g_gru);
    cudaGetSymbolAddress((void**)&p_WpnS, g_WpnS);
    cudaGetSymbolAddress((void**)&p_WihS, g_WihS);
    cudaGetSymbolAddress((void**)&p_WhhS, g_WhhS);
    cudaGetSymbolAddress((void**)&p_WcS,  g_WcS);
    cudaGetSymbolAddress((void**)&p_Wk2S, g_Wk2S);
    cudaGetSymbolAddress((void**)&p_An,   g_Anode);
    cudaGetSymbolAddress((void**)&p_Ac,   g_Actx);
    cudaGetSymbolAddress((void**)&p_Aq,   g_Acat);

    static bool attr_set = false;
    if (!attr_set) {
        cudaFuncSetAttribute(kron_mma, cudaFuncAttributeMaxDynamicSharedMemorySize, 103000);
        attr_set = true;
    }

    int NBv = (V + 63) / 64;

    // zero accumulators
    {
        int n4 = V * D / 4;
        zero_kernel<<<(n4 + 255) / 256, 256>>>((float4*)p_ctx, n4);
        zero_kernel<<<(n4 + 255) / 256, 256>>>((float4*)p_kf,  n4);
        n4 = V / 4;
        zero_kernel<<<(n4 + 255) / 256, 256>>>((float4*)p_asum, n4);
        zero_kernel<<<(n4 + 255) / 256, 256>>>((float4*)p_lmax, n4);
    }

    // pack weights into fragment streams
    pack_w_frag<<<(64 * 128 + 255) / 256, 256>>>(W_pn, 128, 128, 0, p_WpnS);
    pack_w_frag<<<(64 * 384 + 255) / 256, 256>>>(W_ih, 128, 384, 1, p_WihS);
    pack_w_frag<<<(64 * 384 + 255) / 256, 256>>>(W_hh, 128, 384, 1, p_WhhS);
    pack_w_frag<<<(128 * 128 + 255) / 256, 256>>>(Wc, 256, 128, 0, p_WcS);
    pack_wk2<<<(200 * 128 + 255) / 256, 256>>>(Wk2, p_Wk2S);

    // pack node activations (compact)
    pack_act<<<NBv, 256>>>(node, 128, nullptr, 0, 0, p_An, V);

    npj_kernel<<<(V + 3) / 4, 128>>>(node, Wk1, bk1, lnk1_g, lnk1_b, V);
    logits_kernel<<<(E + 3) / 4, 128>>>(node, src, dst, W_edge, b_edge, E);
    expsum_kernel<<<(E + 255) / 256, 256>>>(dst, E);

    // hv = node @ W_pn + b_pn
    mma_gemm<<<dim3(NBv, 1), 256>>>(p_An, p_WpnS, 4, 128,
                                    b_pn, nullptr, nullptr, p_hv, V);

    // edge kron GEMM + LN + relu + atomic scatter
    kron_mma<<<(E + 127) / 128, 256, 102400>>>(src, dst, p_Wk2S,
                                               bk2, lnk2_g, lnk2_b, E);

    // context scatter (float4 atomics)
    context_kernel<<<(E + 7) / 8, 256>>>(src, dst, E);

    // pack relu(ctx)
    pack_act<<<NBv, 256>>>(p_ctx, 128, nullptr, 0, 1, p_Ac, V);

    // gi = relu(ctx) @ W_ih^T + b_ih ; gh = node @ W_hh^T + b_hh
    mma_gemm<<<dim3(NBv, 3), 256>>>(p_Ac, p_WihS, 4, 384,
                                    b_ih, nullptr, nullptr, p_gi, V);
    mma_gemm<<<dim3(NBv, 3), 256>>>(p_An, p_WhhS, 4, 384,
                                    b_hh, nullptr, nullptr, p_gh, V);

    gates_kernel<<<(V + 3) / 4, 128>>>(node, ln_g, ln_b, V);

    // pack cat(gru, kf)
    pack_act<<<NBv, 256>>>(p_gru, 128, p_kf, 128, 0, p_Aq, V);

    // out = relu(LN(cat @ Wc + bc))
    mma_gemm<<<dim3(NBv, 1), 256>>>(p_Aq, p_WcS, 8, 128,
                                    bc, lnc_g, lnc_b, out, V);
}